// round 2
// baseline (speedup 1.0000x reference)
#include <cuda_runtime.h>
#include <math.h>

#define BB 2
#define NN 2048
#define DM 1024
#define HH 16
#define DH 64
#define MROWS (BB*NN)

// Scratch (device globals -- no allocations allowed; referenced directly
// from device code so kernel_launch makes NO host API calls besides launches)
__device__ float g_Q [MROWS*DM];   // [b,h,n,d] head-major
__device__ float g_K [MROWS*DM];
__device__ float g_V [MROWS*DM];
__device__ float g_Vh[MROWS*DM];   // [b,n,h*64+d] row-major

__device__ __forceinline__ float* qkv_buf(int which) {
    return which == 0 ? g_Q : (which == 1 ? g_K : g_V);
}

// ---------------------------------------------------------------------------
// Tiled fp32 GEMM: 64x64x16 tiles, 256 threads, 4x4 per-thread micro-tile.
// MODE 1: out = X * W, head-major scatter into qkv_buf(which)
// MODE 0: out = g_Vh * W + bias, row-major into `out`
// ---------------------------------------------------------------------------
template<int MODE>
__global__ void gemm64(const float* __restrict__ Ain, const float* __restrict__ W,
                       const float* __restrict__ bias, float* __restrict__ outp,
                       int which) {
    const int K = DM, Nout = DM;
    const float* A = (MODE == 0) ? g_Vh : Ain;
    __shared__ float As[64][17];
    __shared__ float Ws[16][65];
    int tid = threadIdx.x;
    int tx = tid & 15, ty = tid >> 4;
    int bm = blockIdx.y * 64, bn = blockIdx.x * 64;
    float acc[4][4] = {};
    for (int k0 = 0; k0 < K; k0 += 16) {
        #pragma unroll
        for (int i = 0; i < 4; i++) {
            int idx = tid + i*256;
            int r = idx >> 4, c = idx & 15;
            As[r][c] = A[(size_t)(bm + r)*K + k0 + c];
        }
        #pragma unroll
        for (int i = 0; i < 4; i++) {
            int idx = tid + i*256;
            int r = idx >> 6, c = idx & 63;
            Ws[r][c] = W[(size_t)(k0 + r)*Nout + bn + c];
        }
        __syncthreads();
        #pragma unroll
        for (int kk = 0; kk < 16; kk++) {
            float a[4], b[4];
            #pragma unroll
            for (int i = 0; i < 4; i++) a[i] = As[ty*4+i][kk];
            #pragma unroll
            for (int j = 0; j < 4; j++) b[j] = Ws[kk][tx*4+j];
            #pragma unroll
            for (int i = 0; i < 4; i++)
                #pragma unroll
                for (int j = 0; j < 4; j++)
                    acc[i][j] = fmaf(a[i], b[j], acc[i][j]);
        }
        __syncthreads();
    }
    float* out = (MODE == 0) ? outp : qkv_buf(which);
    #pragma unroll
    for (int i = 0; i < 4; i++) {
        int m = bm + ty*4 + i;
        #pragma unroll
        for (int j = 0; j < 4; j++) {
            int c = bn + tx*4 + j;
            float v = acc[i][j];
            if (MODE == 0) {
                out[(size_t)m*Nout + c] = v + bias[c];
            } else {
                int b_ = m / NN, n = m % NN;
                int h = c / DH, d = c % DH;
                out[(((size_t)(b_*HH + h))*NN + n)*DH + d] = v;
            }
        }
    }
}

// ---------------------------------------------------------------------------
// Per-head-row L2 normalization: x /= (||x||_2 + 1e-6), row length 64.
// One warp per row.  which: 0 -> g_Q, 1 -> g_K
// ---------------------------------------------------------------------------
__global__ void l2norm(int which, int rows) {
    float* P = qkv_buf(which);
    int warp = (blockIdx.x * blockDim.x + threadIdx.x) >> 5;
    int lane = threadIdx.x & 31;
    if (warp >= rows) return;
    float* p = P + (size_t)warp * DH;
    float x0 = p[lane], x1 = p[lane + 32];
    float ss = x0*x0 + x1*x1;
    #pragma unroll
    for (int o = 16; o; o >>= 1) ss += __shfl_xor_sync(0xffffffffu, ss, o);
    float inv = 1.0f / (sqrtf(ss) + 1e-6f);
    p[lane] = x0 * inv;
    p[lane + 32] = x1 * inv;
}

// ---------------------------------------------------------------------------
// Causal flash attention, fp32.  Block = (bh, q-tile of 64). 256 threads.
// K/V tiles of 32 rows. Online softmax. S and P*V register-blocked.
// ---------------------------------------------------------------------------
__global__ void flash() {
    __shared__ float Qs[64][65];
    __shared__ float Ks[32][65];
    __shared__ float Vs[32][65];
    __shared__ float Ps[64][33];
    int tid = threadIdx.x;
    int tx = tid & 15, ty = tid >> 4;
    int qt = blockIdx.x, bh = blockIdx.y;
    int qbase = qt * 64;
    const float* Qb = g_Q + (size_t)bh * NN * DH;
    const float* Kb = g_K + (size_t)bh * NN * DH;
    const float* Vb = g_V + (size_t)bh * NN * DH;

    #pragma unroll
    for (int i = 0; i < 16; i++) {
        int idx = tid + i*256;
        int r = idx >> 6, c = idx & 63;
        Qs[r][c] = Qb[(size_t)(qbase + r)*DH + c];
    }

    float m_i[4], l_i[4], o[4][4];
    #pragma unroll
    for (int i = 0; i < 4; i++) {
        m_i[i] = -INFINITY; l_i[i] = 0.f;
        #pragma unroll
        for (int j = 0; j < 4; j++) o[i][j] = 0.f;
    }

    const float scale = 0.125f;           // 1/sqrt(64)
    int ktmax = 2*qt + 1;                 // last K tile touching the diagonal
    for (int kt = 0; kt <= ktmax; kt++) {
        int kbase = kt * 32;
        __syncthreads();                  // prior iter done with Ks/Vs/Ps
        #pragma unroll
        for (int i = 0; i < 8; i++) {
            int idx = tid + i*256;
            int r = idx >> 6, c = idx & 63;
            Ks[r][c] = Kb[(size_t)(kbase + r)*DH + c];
            Vs[r][c] = Vb[(size_t)(kbase + r)*DH + c];
        }
        __syncthreads();

        // --- S = Q K^T  (rows ty*4..+3, cols tx*2..+1) ---
        float s[4][2];
        #pragma unroll
        for (int i = 0; i < 4; i++) { s[i][0] = 0.f; s[i][1] = 0.f; }
        #pragma unroll
        for (int kk = 0; kk < 64; kk++) {
            float a[4], bv[2];
            #pragma unroll
            for (int i = 0; i < 4; i++) a[i] = Qs[ty*4+i][kk];
            bv[0] = Ks[tx*2+0][kk];
            bv[1] = Ks[tx*2+1][kk];
            #pragma unroll
            for (int i = 0; i < 4; i++) {
                s[i][0] = fmaf(a[i], bv[0], s[i][0]);
                s[i][1] = fmaf(a[i], bv[1], s[i][1]);
            }
        }

        // --- online softmax (row owned by 16 consecutive lanes) ---
        float alpha[4];
        #pragma unroll
        for (int i = 0; i < 4; i++) {
            int qg = qbase + ty*4 + i;
            float rmax = -INFINITY;
            #pragma unroll
            for (int j = 0; j < 2; j++) {
                int kg = kbase + tx*2 + j;
                float v = s[i][j] * scale;
                if (kg > qg) v = -INFINITY;
                s[i][j] = v;
                rmax = fmaxf(rmax, v);
            }
            #pragma unroll
            for (int off = 8; off; off >>= 1)
                rmax = fmaxf(rmax, __shfl_xor_sync(0xffffffffu, rmax, off));
            float mn = fmaxf(m_i[i], rmax);
            float lsum = 0.f;
            #pragma unroll
            for (int j = 0; j < 2; j++) {
                float p = __expf(s[i][j] - mn);   // exp(-inf - finite) = 0
                Ps[ty*4+i][tx*2+j] = p;
                lsum += p;
            }
            #pragma unroll
            for (int off = 8; off; off >>= 1)
                lsum += __shfl_xor_sync(0xffffffffu, lsum, off);
            alpha[i] = __expf(m_i[i] - mn);
            l_i[i] = l_i[i]*alpha[i] + lsum;
            m_i[i] = mn;
        }
        __syncthreads();

        // --- O = O*alpha + P V  (cols tx*4..+3) ---
        #pragma unroll
        for (int i = 0; i < 4; i++)
            #pragma unroll
            for (int j = 0; j < 4; j++) o[i][j] *= alpha[i];
        #pragma unroll
        for (int c = 0; c < 32; c++) {
            float a[4], bv[4];
            #pragma unroll
            for (int i = 0; i < 4; i++) a[i]  = Ps[ty*4+i][c];
            #pragma unroll
            for (int j = 0; j < 4; j++) bv[j] = Vs[c][tx*4+j];
            #pragma unroll
            for (int i = 0; i < 4; i++)
                #pragma unroll
                for (int j = 0; j < 4; j++)
                    o[i][j] = fmaf(a[i], bv[j], o[i][j]);
        }
    }

    int b_ = bh / HH, h = bh % HH;
    #pragma unroll
    for (int i = 0; i < 4; i++) {
        float invl = 1.0f / l_i[i];
        int q = qbase + ty*4 + i;
        #pragma unroll
        for (int j = 0; j < 4; j++)
            g_Vh[((size_t)(b_*NN + q))*DM + h*DH + tx*4 + j] = o[i][j] * invl;
    }
}

// ---------------------------------------------------------------------------
extern "C" void kernel_launch(void* const* d_in, const int* in_sizes, int n_in,
                              void* d_out, int out_size) {
    const float* X  = (const float*)d_in[0];
    const float* Wq = (const float*)d_in[1];
    const float* Wk = (const float*)d_in[2];
    const float* Wv = (const float*)d_in[3];
    const float* Wo = (const float*)d_in[4];
    const float* bo = (const float*)d_in[5];
    float* out = (float*)d_out;

    dim3 ggrid(DM/64, MROWS/64);   // (16, 64)
    gemm64<1><<<ggrid, 256>>>(X, Wq, nullptr, nullptr, 0);
    gemm64<1><<<ggrid, 256>>>(X, Wk, nullptr, nullptr, 1);
    gemm64<1><<<ggrid, 256>>>(X, Wv, nullptr, nullptr, 2);

    int rows = BB*HH*NN;                       // 65536
    int nblk = (rows*32 + 255) / 256;          // 8192
    l2norm<<<nblk, 256>>>(0, rows);
    l2norm<<<nblk, 256>>>(1, rows);

    flash<<<dim3(NN/64, BB*HH), 256>>>();

    gemm64<0><<<ggrid, 256>>>(nullptr, Wo, bo, out, 0);
}

// round 3
// speedup vs baseline: 1.4069x; 1.4069x over previous
#include <cuda_runtime.h>
#include <math.h>
#include <mma.h>

using namespace nvcuda;

#define BB 2
#define NN 2048
#define DM 1024
#define HH 16
#define DH 64
#define MROWS (BB*NN)

// Scratch (device globals -- no allocations allowed)
__device__ float g_Q [MROWS*DM];   // [b,h,n,d] head-major
__device__ float g_K [MROWS*DM];
__device__ float g_V [MROWS*DM];
__device__ float g_Vh[MROWS*DM];   // [b,n,h*64+d] row-major

__device__ __forceinline__ float* qkv_buf(int which) {
    return which == 0 ? g_Q : (which == 1 ? g_K : g_V);
}

// ---------------------------------------------------------------------------
// tf32 tensor-core GEMM: C[M,1024] = A[M,1024] * W[1024,1024] (+bias)
// Block tile 128x128, K-tile 32, 256 threads (8 warps, each 64x32 via
// 4x2 m16n16k8 wmma accumulators).
// MODE 1: head-major scatter into qkv_buf(which) (no bias)
// MODE 0: A = g_Vh, row-major out + bias (bias pre-loaded into accumulators)
// ---------------------------------------------------------------------------
#define TM 128
#define TN 128
#define TK 32

template<int MODE>
__global__ void gemm_tf32(const float* __restrict__ Ain,
                          const float* __restrict__ W,
                          const float* __restrict__ bias,
                          float* __restrict__ outp, int which) {
    const float* A = (MODE == 0) ? g_Vh : Ain;
    __shared__ float As[TM][TK + 4];    // 128 x 36
    __shared__ float Ws[TK][TN + 4];    // 32 x 132
    __shared__ float Bs[16][TN + 4];    // bias replicated rows (MODE 0)

    int tid  = threadIdx.x;
    int warp = tid >> 5;
    int wm   = warp >> 2;               // 0..1
    int wn   = warp & 3;                // 0..3
    int bm = blockIdx.y * TM, bn = blockIdx.x * TN;

    wmma::fragment<wmma::accumulator, 16, 16, 8, float> acc[4][2];

    if (MODE == 0) {
        // replicate bias across 16 rows so accumulators can be seeded from it
        for (int idx = tid; idx < 16 * TN; idx += 256) {
            int r = idx >> 7, c = idx & 127;
            Bs[r][c] = bias[bn + c];
        }
        __syncthreads();
        #pragma unroll
        for (int i = 0; i < 4; i++)
            #pragma unroll
            for (int j = 0; j < 2; j++)
                wmma::load_matrix_sync(acc[i][j], &Bs[0][wn*32 + j*16],
                                       TN + 4, wmma::mem_row_major);
        __syncthreads();
    } else {
        #pragma unroll
        for (int i = 0; i < 4; i++)
            #pragma unroll
            for (int j = 0; j < 2; j++)
                wmma::fill_fragment(acc[i][j], 0.0f);
    }

    for (int k0 = 0; k0 < DM; k0 += TK) {
        // A tile: 128x32 = 1024 float4
        #pragma unroll
        for (int i = 0; i < 4; i++) {
            int idx = tid + i*256;
            int r = idx >> 3, c4 = idx & 7;
            float4 v = *(const float4*)&A[(size_t)(bm + r)*DM + k0 + c4*4];
            As[r][c4*4+0] = wmma::__float_to_tf32(v.x);
            As[r][c4*4+1] = wmma::__float_to_tf32(v.y);
            As[r][c4*4+2] = wmma::__float_to_tf32(v.z);
            As[r][c4*4+3] = wmma::__float_to_tf32(v.w);
        }
        // W tile: 32x128 = 1024 float4
        #pragma unroll
        for (int i = 0; i < 4; i++) {
            int idx = tid + i*256;
            int r = idx >> 5, c4 = idx & 31;
            float4 v = *(const float4*)&W[(size_t)(k0 + r)*DM + bn + c4*4];
            Ws[r][c4*4+0] = wmma::__float_to_tf32(v.x);
            Ws[r][c4*4+1] = wmma::__float_to_tf32(v.y);
            Ws[r][c4*4+2] = wmma::__float_to_tf32(v.z);
            Ws[r][c4*4+3] = wmma::__float_to_tf32(v.w);
        }
        __syncthreads();

        #pragma unroll
        for (int kk = 0; kk < TK; kk += 8) {
            wmma::fragment<wmma::matrix_a, 16, 16, 8, wmma::precision::tf32, wmma::row_major> af[4];
            wmma::fragment<wmma::matrix_b, 16, 16, 8, wmma::precision::tf32, wmma::row_major> bf[2];
            #pragma unroll
            for (int i = 0; i < 4; i++)
                wmma::load_matrix_sync(af[i], &As[wm*64 + i*16][kk], TK + 4);
            #pragma unroll
            for (int j = 0; j < 2; j++)
                wmma::load_matrix_sync(bf[j], &Ws[kk][wn*32 + j*16], TN + 4);
            #pragma unroll
            for (int i = 0; i < 4; i++)
                #pragma unroll
                for (int j = 0; j < 2; j++)
                    wmma::mma_sync(acc[i][j], af[i], bf[j], acc[i][j]);
        }
        __syncthreads();
    }

    if (MODE == 0) {
        #pragma unroll
        for (int i = 0; i < 4; i++)
            #pragma unroll
            for (int j = 0; j < 2; j++)
                wmma::store_matrix_sync(
                    &outp[(size_t)(bm + wm*64 + i*16)*DM + bn + wn*32 + j*16],
                    acc[i][j], DM, wmma::mem_row_major);
    } else {
        float* out = qkv_buf(which);
        #pragma unroll
        for (int i = 0; i < 4; i++) {
            int m = bm + wm*64 + i*16;
            int b_ = m / NN, n = m % NN;          // 128-row tiles never cross batch
            #pragma unroll
            for (int j = 0; j < 2; j++) {
                int c = bn + wn*32 + j*16;
                int h = c >> 6, d = c & 63;        // 16 cols stay within one head
                float* p = out + (((size_t)(b_*HH + h))*NN + n)*DH + d;
                wmma::store_matrix_sync(p, acc[i][j], DH, wmma::mem_row_major);
            }
        }
    }
}

// ---------------------------------------------------------------------------
// Per-head-row L2 normalization. One warp per row of 64.
// ---------------------------------------------------------------------------
__global__ void l2norm(int which, int rows) {
    float* P = qkv_buf(which);
    int warp = (blockIdx.x * blockDim.x + threadIdx.x) >> 5;
    int lane = threadIdx.x & 31;
    if (warp >= rows) return;
    float* p = P + (size_t)warp * DH;
    float x0 = p[lane], x1 = p[lane + 32];
    float ss = x0*x0 + x1*x1;
    #pragma unroll
    for (int o = 16; o; o >>= 1) ss += __shfl_xor_sync(0xffffffffu, ss, o);
    float inv = 1.0f / (sqrtf(ss) + 1e-6f);
    p[lane] = x0 * inv;
    p[lane + 32] = x1 * inv;
}

// ---------------------------------------------------------------------------
// Causal flash attention, fp32 scalar (unchanged this round).
// ---------------------------------------------------------------------------
__global__ void flash() {
    __shared__ float Qs[64][65];
    __shared__ float Ks[32][65];
    __shared__ float Vs[32][65];
    __shared__ float Ps[64][33];
    int tid = threadIdx.x;
    int tx = tid & 15, ty = tid >> 4;
    int qt = blockIdx.x, bh = blockIdx.y;
    int qbase = qt * 64;
    const float* Qb = g_Q + (size_t)bh * NN * DH;
    const float* Kb = g_K + (size_t)bh * NN * DH;
    const float* Vb = g_V + (size_t)bh * NN * DH;

    #pragma unroll
    for (int i = 0; i < 16; i++) {
        int idx = tid + i*256;
        int r = idx >> 6, c = idx & 63;
        Qs[r][c] = Qb[(size_t)(qbase + r)*DH + c];
    }

    float m_i[4], l_i[4], o[4][4];
    #pragma unroll
    for (int i = 0; i < 4; i++) {
        m_i[i] = -INFINITY; l_i[i] = 0.f;
        #pragma unroll
        for (int j = 0; j < 4; j++) o[i][j] = 0.f;
    }

    const float scale = 0.125f;
    int ktmax = 2*qt + 1;
    for (int kt = 0; kt <= ktmax; kt++) {
        int kbase = kt * 32;
        __syncthreads();
        #pragma unroll
        for (int i = 0; i < 8; i++) {
            int idx = tid + i*256;
            int r = idx >> 6, c = idx & 63;
            Ks[r][c] = Kb[(size_t)(kbase + r)*DH + c];
            Vs[r][c] = Vb[(size_t)(kbase + r)*DH + c];
        }
        __syncthreads();

        float s[4][2];
        #pragma unroll
        for (int i = 0; i < 4; i++) { s[i][0] = 0.f; s[i][1] = 0.f; }
        #pragma unroll
        for (int kk = 0; kk < 64; kk++) {
            float a[4], bv[2];
            #pragma unroll
            for (int i = 0; i < 4; i++) a[i] = Qs[ty*4+i][kk];
            bv[0] = Ks[tx*2+0][kk];
            bv[1] = Ks[tx*2+1][kk];
            #pragma unroll
            for (int i = 0; i < 4; i++) {
                s[i][0] = fmaf(a[i], bv[0], s[i][0]);
                s[i][1] = fmaf(a[i], bv[1], s[i][1]);
            }
        }

        float alpha[4];
        #pragma unroll
        for (int i = 0; i < 4; i++) {
            int qg = qbase + ty*4 + i;
            float rmax = -INFINITY;
            #pragma unroll
            for (int j = 0; j < 2; j++) {
                int kg = kbase + tx*2 + j;
                float v = s[i][j] * scale;
                if (kg > qg) v = -INFINITY;
                s[i][j] = v;
                rmax = fmaxf(rmax, v);
            }
            #pragma unroll
            for (int off = 8; off; off >>= 1)
                rmax = fmaxf(rmax, __shfl_xor_sync(0xffffffffu, rmax, off));
            float mn = fmaxf(m_i[i], rmax);
            float lsum = 0.f;
            #pragma unroll
            for (int j = 0; j < 2; j++) {
                float p = __expf(s[i][j] - mn);
                Ps[ty*4+i][tx*2+j] = p;
                lsum += p;
            }
            #pragma unroll
            for (int off = 8; off; off >>= 1)
                lsum += __shfl_xor_sync(0xffffffffu, lsum, off);
            alpha[i] = __expf(m_i[i] - mn);
            l_i[i] = l_i[i]*alpha[i] + lsum;
            m_i[i] = mn;
        }
        __syncthreads();

        #pragma unroll
        for (int i = 0; i < 4; i++)
            #pragma unroll
            for (int j = 0; j < 4; j++) o[i][j] *= alpha[i];
        #pragma unroll
        for (int c = 0; c < 32; c++) {
            float a[4], bv[4];
            #pragma unroll
            for (int i = 0; i < 4; i++) a[i]  = Ps[ty*4+i][c];
            #pragma unroll
            for (int j = 0; j < 4; j++) bv[j] = Vs[c][tx*4+j];
            #pragma unroll
            for (int i = 0; i < 4; i++)
                #pragma unroll
                for (int j = 0; j < 4; j++)
                    o[i][j] = fmaf(a[i], bv[j], o[i][j]);
        }
    }

    int b_ = bh / HH, h = bh % HH;
    #pragma unroll
    for (int i = 0; i < 4; i++) {
        float invl = 1.0f / l_i[i];
        int q = qbase + ty*4 + i;
        #pragma unroll
        for (int j = 0; j < 4; j++)
            g_Vh[((size_t)(b_*NN + q))*DM + h*DH + tx*4 + j] = o[i][j] * invl;
    }
}

// ---------------------------------------------------------------------------
extern "C" void kernel_launch(void* const* d_in, const int* in_sizes, int n_in,
                              void* d_out, int out_size) {
    const float* X  = (const float*)d_in[0];
    const float* Wq = (const float*)d_in[1];
    const float* Wk = (const float*)d_in[2];
    const float* Wv = (const float*)d_in[3];
    const float* Wo = (const float*)d_in[4];
    const float* bo = (const float*)d_in[5];
    float* out = (float*)d_out;

    dim3 ggrid(DM/TN, MROWS/TM);   // (8, 32)
    gemm_tf32<1><<<ggrid, 256>>>(X, Wq, nullptr, nullptr, 0);
    gemm_tf32<1><<<ggrid, 256>>>(X, Wk, nullptr, nullptr, 1);
    gemm_tf32<1><<<ggrid, 256>>>(X, Wv, nullptr, nullptr, 2);

    int rows = BB*HH*NN;                       // 65536
    int nblk = (rows*32 + 255) / 256;          // 8192
    l2norm<<<nblk, 256>>>(0, rows);
    l2norm<<<nblk, 256>>>(1, rows);

    flash<<<dim3(NN/64, BB*HH), 256>>>();

    gemm_tf32<0><<<ggrid, 256>>>(nullptr, Wo, bo, out, 0);
}

// round 4
// speedup vs baseline: 1.5106x; 1.0737x over previous
#include <cuda_runtime.h>
#include <math.h>
#include <mma.h>

using namespace nvcuda;

#define BB 2
#define NN 2048
#define DM 1024
#define HH 16
#define DH 64
#define MROWS (BB*NN)

// Scratch (device globals -- no allocations allowed)
__device__ float g_Q [MROWS*DM];   // [b,h,n,d] head-major
__device__ float g_K [MROWS*DM];
__device__ float g_V [MROWS*DM];
__device__ float g_Vh[MROWS*DM];   // [b,n,h*64+d] row-major

__device__ __forceinline__ float* qkv_buf(int which) {
    return which == 0 ? g_Q : (which == 1 ? g_K : g_V);
}

// ---------------------------------------------------------------------------
// tf32 tensor-core GEMM (unchanged from R3): 128x128x32 tiles, 256 threads.
// ---------------------------------------------------------------------------
#define TM 128
#define TN 128
#define TK 32

template<int MODE>
__global__ void gemm_tf32(const float* __restrict__ Ain,
                          const float* __restrict__ W,
                          const float* __restrict__ bias,
                          float* __restrict__ outp, int which) {
    const float* A = (MODE == 0) ? g_Vh : Ain;
    __shared__ float As[TM][TK + 4];
    __shared__ float Ws[TK][TN + 4];
    __shared__ float Bs[16][TN + 4];

    int tid  = threadIdx.x;
    int warp = tid >> 5;
    int wm   = warp >> 2;
    int wn   = warp & 3;
    int bm = blockIdx.y * TM, bn = blockIdx.x * TN;

    wmma::fragment<wmma::accumulator, 16, 16, 8, float> acc[4][2];

    if (MODE == 0) {
        for (int idx = tid; idx < 16 * TN; idx += 256) {
            int r = idx >> 7, c = idx & 127;
            Bs[r][c] = bias[bn + c];
        }
        __syncthreads();
        #pragma unroll
        for (int i = 0; i < 4; i++)
            #pragma unroll
            for (int j = 0; j < 2; j++)
                wmma::load_matrix_sync(acc[i][j], &Bs[0][wn*32 + j*16],
                                       TN + 4, wmma::mem_row_major);
        __syncthreads();
    } else {
        #pragma unroll
        for (int i = 0; i < 4; i++)
            #pragma unroll
            for (int j = 0; j < 2; j++)
                wmma::fill_fragment(acc[i][j], 0.0f);
    }

    for (int k0 = 0; k0 < DM; k0 += TK) {
        #pragma unroll
        for (int i = 0; i < 4; i++) {
            int idx = tid + i*256;
            int r = idx >> 3, c4 = idx & 7;
            float4 v = *(const float4*)&A[(size_t)(bm + r)*DM + k0 + c4*4];
            As[r][c4*4+0] = wmma::__float_to_tf32(v.x);
            As[r][c4*4+1] = wmma::__float_to_tf32(v.y);
            As[r][c4*4+2] = wmma::__float_to_tf32(v.z);
            As[r][c4*4+3] = wmma::__float_to_tf32(v.w);
        }
        #pragma unroll
        for (int i = 0; i < 4; i++) {
            int idx = tid + i*256;
            int r = idx >> 5, c4 = idx & 31;
            float4 v = *(const float4*)&W[(size_t)(k0 + r)*DM + bn + c4*4];
            Ws[r][c4*4+0] = wmma::__float_to_tf32(v.x);
            Ws[r][c4*4+1] = wmma::__float_to_tf32(v.y);
            Ws[r][c4*4+2] = wmma::__float_to_tf32(v.z);
            Ws[r][c4*4+3] = wmma::__float_to_tf32(v.w);
        }
        __syncthreads();

        #pragma unroll
        for (int kk = 0; kk < TK; kk += 8) {
            wmma::fragment<wmma::matrix_a, 16, 16, 8, wmma::precision::tf32, wmma::row_major> af[4];
            wmma::fragment<wmma::matrix_b, 16, 16, 8, wmma::precision::tf32, wmma::row_major> bf[2];
            #pragma unroll
            for (int i = 0; i < 4; i++)
                wmma::load_matrix_sync(af[i], &As[wm*64 + i*16][kk], TK + 4);
            #pragma unroll
            for (int j = 0; j < 2; j++)
                wmma::load_matrix_sync(bf[j], &Ws[kk][wn*32 + j*16], TN + 4);
            #pragma unroll
            for (int i = 0; i < 4; i++)
                #pragma unroll
                for (int j = 0; j < 2; j++)
                    wmma::mma_sync(acc[i][j], af[i], bf[j], acc[i][j]);
        }
        __syncthreads();
    }

    if (MODE == 0) {
        #pragma unroll
        for (int i = 0; i < 4; i++)
            #pragma unroll
            for (int j = 0; j < 2; j++)
                wmma::store_matrix_sync(
                    &outp[(size_t)(bm + wm*64 + i*16)*DM + bn + wn*32 + j*16],
                    acc[i][j], DM, wmma::mem_row_major);
    } else {
        float* out = qkv_buf(which);
        #pragma unroll
        for (int i = 0; i < 4; i++) {
            int m = bm + wm*64 + i*16;
            int b_ = m / NN, n = m % NN;
            #pragma unroll
            for (int j = 0; j < 2; j++) {
                int c = bn + wn*32 + j*16;
                int h = c >> 6, d = c & 63;
                float* p = out + (((size_t)(b_*HH + h))*NN + n)*DH + d;
                wmma::store_matrix_sync(p, acc[i][j], DH, wmma::mem_row_major);
            }
        }
    }
}

// ---------------------------------------------------------------------------
// Per-head-row L2 normalization. One warp per row of 64.
// ---------------------------------------------------------------------------
__global__ void l2norm(int which, int rows) {
    float* P = qkv_buf(which);
    int warp = (blockIdx.x * blockDim.x + threadIdx.x) >> 5;
    int lane = threadIdx.x & 31;
    if (warp >= rows) return;
    float* p = P + (size_t)warp * DH;
    float x0 = p[lane], x1 = p[lane + 32];
    float ss = x0*x0 + x1*x1;
    #pragma unroll
    for (int o = 16; o; o >>= 1) ss += __shfl_xor_sync(0xffffffffu, ss, o);
    float inv = 1.0f / (sqrtf(ss) + 1e-6f);
    p[lane] = x0 * inv;
    p[lane + 32] = x1 * inv;
}

// ---------------------------------------------------------------------------
// Causal attention, tensor-core tf32.
// KEY INVARIANT: Q,K rows are unit-L2 => scores in [-0.125, 0.125], so
// softmax needs NO running max and NO rescale: P = exp(s), l = sum P,
// O accumulates in wmma fragments across the whole KV loop.
// Block = (q-tile of 64, bh). 256 threads = 8 warps.
// S tile 64x32 (warp w -> 16x16 tile (w>>1, w&1)).
// O tile 64x64 (warp w -> rows (w>>1)*16, cols (w&1)*32, two 16x16 frags).
// ---------------------------------------------------------------------------
__global__ void flash() {
    __shared__ float Qs[64][68];   // Q tile (tf32); reused for O in epilogue
    __shared__ float Ks[32][68];
    __shared__ float Vs[32][68];
    __shared__ float Ps[64][36];   // S then P (tf32)

    int tid = threadIdx.x;
    int warp = tid >> 5;
    int wm = warp >> 1, wn = warp & 1;
    int qt = blockIdx.x, bh = blockIdx.y;
    int qbase = qt * 64;
    const float* Qb = g_Q + (size_t)bh * NN * DH;
    const float* Kb = g_K + (size_t)bh * NN * DH;
    const float* Vb = g_V + (size_t)bh * NN * DH;

    #pragma unroll
    for (int i = 0; i < 16; i++) {
        int idx = tid + i*256;
        int r = idx >> 6, c = idx & 63;
        Qs[r][c] = wmma::__float_to_tf32(Qb[(size_t)(qbase + r)*DH + c]);
    }

    wmma::fragment<wmma::accumulator, 16, 16, 8, float> oacc[2];
    wmma::fill_fragment(oacc[0], 0.0f);
    wmma::fill_fragment(oacc[1], 0.0f);

    float l_part = 0.0f;
    int prow = tid >> 2;              // 0..63
    int pc0  = (tid & 3) * 8;         // 0,8,16,24

    int ktmax = 2*qt + 1;
    for (int kt = 0; kt <= ktmax; kt++) {
        int kbase = kt * 32;
        __syncthreads();              // prev iter done with Ks/Vs/Ps
        #pragma unroll
        for (int i = 0; i < 8; i++) {
            int idx = tid + i*256;
            int r = idx >> 6, c = idx & 63;
            Ks[r][c] = wmma::__float_to_tf32(Kb[(size_t)(kbase + r)*DH + c]);
            Vs[r][c] = wmma::__float_to_tf32(Vb[(size_t)(kbase + r)*DH + c]);
        }
        __syncthreads();

        // --- S = Q K^T : warp tile (wm, wn) of 64x32 ---
        {
            wmma::fragment<wmma::accumulator, 16, 16, 8, float> s;
            wmma::fill_fragment(s, 0.0f);
            #pragma unroll
            for (int kk = 0; kk < 64; kk += 8) {
                wmma::fragment<wmma::matrix_a, 16, 16, 8, wmma::precision::tf32, wmma::row_major> a;
                wmma::fragment<wmma::matrix_b, 16, 16, 8, wmma::precision::tf32, wmma::col_major> b;
                wmma::load_matrix_sync(a, &Qs[wm*16][kk], 68);
                wmma::load_matrix_sync(b, &Ks[wn*16][kk], 68);   // K row-major == B col-major
                wmma::mma_sync(s, a, b, s);
            }
            wmma::store_matrix_sync(&Ps[wm*16][wn*16], s, 36, wmma::mem_row_major);
        }
        __syncthreads();

        // --- P = exp(mask(S/8)); accumulate row sums ---
        bool diag = (kt >= 2*qt);
        float psum = 0.0f;
        #pragma unroll
        for (int j = 0; j < 8; j++) {
            int col = pc0 + j;
            float sv = Ps[prow][col] * 0.125f;
            float p = __expf(sv);
            if (diag && (kbase + col > qbase + prow)) p = 0.0f;
            Ps[prow][col] = wmma::__float_to_tf32(p);
            psum += p;
        }
        l_part += psum;
        __syncthreads();

        // --- O += P V : warp rows wm*16, cols wn*32 + {0,16} ---
        #pragma unroll
        for (int kk = 0; kk < 32; kk += 8) {
            wmma::fragment<wmma::matrix_a, 16, 16, 8, wmma::precision::tf32, wmma::row_major> a;
            wmma::fragment<wmma::matrix_b, 16, 16, 8, wmma::precision::tf32, wmma::row_major> b0, b1;
            wmma::load_matrix_sync(a, &Ps[wm*16][kk], 36);
            wmma::load_matrix_sync(b0, &Vs[kk][wn*32], 68);
            wmma::load_matrix_sync(b1, &Vs[kk][wn*32 + 16], 68);
            wmma::mma_sync(oacc[0], a, b0, oacc[0]);
            wmma::mma_sync(oacc[1], a, b1, oacc[1]);
        }
    }

    // --- epilogue: O -> smem (reuse Qs), normalize by row sum, write ---
    __syncthreads();
    wmma::store_matrix_sync(&Qs[wm*16][wn*32],      oacc[0], 68, wmma::mem_row_major);
    wmma::store_matrix_sync(&Qs[wm*16][wn*32 + 16], oacc[1], 68, wmma::mem_row_major);

    float l = l_part;
    l += __shfl_xor_sync(0xffffffffu, l, 1);
    l += __shfl_xor_sync(0xffffffffu, l, 2);
    __syncthreads();

    float invl = 1.0f / l;
    int b_ = bh / HH, h = bh % HH;
    int q = qbase + prow;
    float* dst = g_Vh + ((size_t)(b_*NN + q))*DM + h*DH + (tid & 3)*16;
    #pragma unroll
    for (int j = 0; j < 16; j++)
        dst[j] = Qs[prow][(tid & 3)*16 + j] * invl;
}

// ---------------------------------------------------------------------------
extern "C" void kernel_launch(void* const* d_in, const int* in_sizes, int n_in,
                              void* d_out, int out_size) {
    const float* X  = (const float*)d_in[0];
    const float* Wq = (const float*)d_in[1];
    const float* Wk = (const float*)d_in[2];
    const float* Wv = (const float*)d_in[3];
    const float* Wo = (const float*)d_in[4];
    const float* bo = (const float*)d_in[5];
    float* out = (float*)d_out;

    dim3 ggrid(DM/TN, MROWS/TM);   // (8, 32)
    gemm_tf32<1><<<ggrid, 256>>>(X, Wq, nullptr, nullptr, 0);
    gemm_tf32<1><<<ggrid, 256>>>(X, Wk, nullptr, nullptr, 1);
    gemm_tf32<1><<<ggrid, 256>>>(X, Wv, nullptr, nullptr, 2);

    int rows = BB*HH*NN;                       // 65536
    int nblk = (rows*32 + 255) / 256;          // 8192
    l2norm<<<nblk, 256>>>(0, rows);
    l2norm<<<nblk, 256>>>(1, rows);

    flash<<<dim3(NN/64, BB*HH), 256>>>();

    gemm_tf32<0><<<ggrid, 256>>>(nullptr, Wo, bo, out, 0);
}

// round 6
// speedup vs baseline: 2.1719x; 1.4378x over previous
#include <cuda_runtime.h>
#include <math.h>
#include <mma.h>
#include <cuda_bf16.h>
#include <cuda_fp16.h>

using namespace nvcuda;

#define BB 2
#define NN 2048
#define DM 1024
#define HH 16
#define DH 64
#define MROWS (BB*NN)

// Scratch (device globals -- no allocations allowed)
__device__ float g_Q [MROWS*DM];           // fp32 [b,h,n,d] head-major
__device__ float g_K [MROWS*DM];
__device__ float g_V [MROWS*DM];
__device__ float g_Vh[MROWS*DM];           // UNNORMALIZED O, [b,n,h*64+d]
__device__ __nv_bfloat16 g_Qb[MROWS*DM];   // normalized Q, bf16
__device__ __nv_bfloat16 g_Kb[MROWS*DM];   // normalized K, bf16
__device__ __half        g_Vx[MROWS*DM];   // V, fp16
__device__ float g_L[BB*HH*NN];            // 1/l per (b,h,q)

__device__ __forceinline__ float* qkv_buf(int which) {
    return which == 0 ? g_Q : (which == 1 ? g_K : g_V);
}

// ---------------------------------------------------------------------------
// tf32 tensor-core GEMM: 128x128x32 tiles, 256 threads.
// MODE 1: X*W -> head-major fp32 scatter into qkv_buf(which)
// MODE 0: (g_Vh * diag-scale) * Wo + bias -> row-major out.
//         A rows are scaled by g_L[(b,h(k0),n)] on load (attention 1/l).
// ---------------------------------------------------------------------------
#define TM 128
#define TN 128
#define TK 32

template<int MODE>
__global__ void gemm_tf32(const float* __restrict__ Ain,
                          const float* __restrict__ W,
                          const float* __restrict__ bias,
                          float* __restrict__ outp, int which) {
    const float* A = (MODE == 0) ? g_Vh : Ain;
    __shared__ float As[TM][TK + 4];
    __shared__ float Ws[TK][TN + 4];
    __shared__ float Bs[16][TN + 4];

    int tid  = threadIdx.x;
    int warp = tid >> 5;
    int wm   = warp >> 2;
    int wn   = warp & 3;
    int bm = blockIdx.y * TM, bn = blockIdx.x * TN;

    wmma::fragment<wmma::accumulator, 16, 16, 8, float> acc[4][2];

    if (MODE == 0) {
        for (int idx = tid; idx < 16 * TN; idx += 256) {
            int r = idx >> 7, c = idx & 127;
            Bs[r][c] = bias[bn + c];
        }
        __syncthreads();
        #pragma unroll
        for (int i = 0; i < 4; i++)
            #pragma unroll
            for (int j = 0; j < 2; j++)
                wmma::load_matrix_sync(acc[i][j], &Bs[0][wn*32 + j*16],
                                       TN + 4, wmma::mem_row_major);
        __syncthreads();
    } else {
        #pragma unroll
        for (int i = 0; i < 4; i++)
            #pragma unroll
            for (int j = 0; j < 2; j++)
                wmma::fill_fragment(acc[i][j], 0.0f);
    }

    for (int k0 = 0; k0 < DM; k0 += TK) {
        #pragma unroll
        for (int i = 0; i < 4; i++) {
            int idx = tid + i*256;
            int r = idx >> 3, c4 = idx & 7;
            int m = bm + r;
            float4 v = *(const float4*)&A[(size_t)m*DM + k0 + c4*4];
            float sc = 1.0f;
            if (MODE == 0) {
                int b_ = m >> 11, n = m & (NN-1);
                sc = g_L[((b_*HH + (k0 >> 6)))*NN + n];
            }
            As[r][c4*4+0] = wmma::__float_to_tf32(v.x * sc);
            As[r][c4*4+1] = wmma::__float_to_tf32(v.y * sc);
            As[r][c4*4+2] = wmma::__float_to_tf32(v.z * sc);
            As[r][c4*4+3] = wmma::__float_to_tf32(v.w * sc);
        }
        #pragma unroll
        for (int i = 0; i < 4; i++) {
            int idx = tid + i*256;
            int r = idx >> 5, c4 = idx & 31;
            float4 v = *(const float4*)&W[(size_t)(k0 + r)*DM + bn + c4*4];
            Ws[r][c4*4+0] = wmma::__float_to_tf32(v.x);
            Ws[r][c4*4+1] = wmma::__float_to_tf32(v.y);
            Ws[r][c4*4+2] = wmma::__float_to_tf32(v.z);
            Ws[r][c4*4+3] = wmma::__float_to_tf32(v.w);
        }
        __syncthreads();

        #pragma unroll
        for (int kk = 0; kk < TK; kk += 8) {
            wmma::fragment<wmma::matrix_a, 16, 16, 8, wmma::precision::tf32, wmma::row_major> af[4];
            wmma::fragment<wmma::matrix_b, 16, 16, 8, wmma::precision::tf32, wmma::row_major> bf[2];
            #pragma unroll
            for (int i = 0; i < 4; i++)
                wmma::load_matrix_sync(af[i], &As[wm*64 + i*16][kk], TK + 4);
            #pragma unroll
            for (int j = 0; j < 2; j++)
                wmma::load_matrix_sync(bf[j], &Ws[kk][wn*32 + j*16], TN + 4);
            #pragma unroll
            for (int i = 0; i < 4; i++)
                #pragma unroll
                for (int j = 0; j < 2; j++)
                    wmma::mma_sync(acc[i][j], af[i], bf[j], acc[i][j]);
        }
        __syncthreads();
    }

    if (MODE == 0) {
        #pragma unroll
        for (int i = 0; i < 4; i++)
            #pragma unroll
            for (int j = 0; j < 2; j++)
                wmma::store_matrix_sync(
                    &outp[(size_t)(bm + wm*64 + i*16)*DM + bn + wn*32 + j*16],
                    acc[i][j], DM, wmma::mem_row_major);
    } else {
        float* out = qkv_buf(which);
        #pragma unroll
        for (int i = 0; i < 4; i++) {
            int m = bm + wm*64 + i*16;
            int b_ = m / NN, n = m % NN;
            #pragma unroll
            for (int j = 0; j < 2; j++) {
                int c = bn + wn*32 + j*16;
                int h = c >> 6, d = c & 63;
                float* p = out + (((size_t)(b_*HH + h))*NN + n)*DH + d;
                wmma::store_matrix_sync(p, acc[i][j], DH, wmma::mem_row_major);
            }
        }
    }
}

// ---------------------------------------------------------------------------
// L2 normalize rows of 64 and convert to bf16. One warp per row.
// which: 0 -> g_Q->g_Qb, 1 -> g_K->g_Kb
// ---------------------------------------------------------------------------
__global__ void l2norm_cvt(int which, int rows) {
    const float* P = (which == 0) ? g_Q : g_K;
    __nv_bfloat16* O = (which == 0) ? g_Qb : g_Kb;
    int warp = (blockIdx.x * blockDim.x + threadIdx.x) >> 5;
    int lane = threadIdx.x & 31;
    if (warp >= rows) return;
    const float* p = P + (size_t)warp * DH;
    float x0 = p[lane], x1 = p[lane + 32];
    float ss = x0*x0 + x1*x1;
    #pragma unroll
    for (int o = 16; o; o >>= 1) ss += __shfl_xor_sync(0xffffffffu, ss, o);
    float inv = 1.0f / (sqrtf(ss) + 1e-6f);
    __nv_bfloat16* q = O + (size_t)warp * DH;
    q[lane]      = __float2bfloat16(x0 * inv);
    q[lane + 32] = __float2bfloat16(x1 * inv);
}

// V fp32 -> fp16
__global__ void vcvt() {
    int i = blockIdx.x * blockDim.x + threadIdx.x;   // float4 index
    const float4* src = (const float4*)g_V;
    __half2* dst = (__half2*)g_Vx;
    float4 v = src[i];
    dst[2*i]   = __floats2half2_rn(v.x, v.y);
    dst[2*i+1] = __floats2half2_rn(v.z, v.w);
}

// ---------------------------------------------------------------------------
// Causal attention, bf16 (S) + fp16 (PV) tensor cores.
// Unit-norm Q,K => scores in [-0.125,0.125]: no running max, no rescale.
// Block = (q-tile 64, bh), 256 threads / 8 warps.
// Writes UNNORMALIZED O to g_Vh and 1/l to g_L (folded into output GEMM).
// ---------------------------------------------------------------------------
__global__ void flash() {
    __shared__ __nv_bfloat16 Qs[64][72];
    __shared__ __nv_bfloat16 Ks[32][72];
    __shared__ __half        Vs[32][72];
    __shared__ float         Ps[64][36];   // raw S scores
    __shared__ __half        Pf[64][40];   // exp'd P, fp16

    int tid = threadIdx.x;
    int warp = tid >> 5;
    int wm = warp >> 1, wn = warp & 1;     // S: 4x2 warp tiles of 16x16
    int qt = blockIdx.x, bh = blockIdx.y;
    int qbase = qt * 64;
    const __nv_bfloat16* Qb = g_Qb + (size_t)bh * NN * DH;
    const __nv_bfloat16* Kb = g_Kb + (size_t)bh * NN * DH;
    const __half*        Vb = g_Vx + (size_t)bh * NN * DH;

    // Q tile: 64x64 bf16, thread loads 16 elems (2 x uint4)
    {
        int r = tid >> 2, c0 = (tid & 3) * 16;
        const uint4* s = (const uint4*)(Qb + (size_t)(qbase + r)*DH + c0);
        *(uint4*)&Qs[r][c0]     = s[0];
        *(uint4*)&Qs[r][c0 + 8] = s[1];
    }

    wmma::fragment<wmma::accumulator, 16, 16, 16, float> oacc[2];
    wmma::fill_fragment(oacc[0], 0.0f);
    wmma::fill_fragment(oacc[1], 0.0f);

    float l_part = 0.0f;
    int prow = tid >> 2;              // 0..63
    int pc0  = (tid & 3) * 8;         // 0,8,16,24

    // K/V prefetch: tile 32x64, thread owns 8 elems (1 uint4)
    int kr = tid >> 3, kc = (tid & 7) * 8;
    int ktmax = 2*qt + 1;
    uint4 kreg = *(const uint4*)(Kb + (size_t)kr*DH + kc);
    uint4 vreg = *(const uint4*)(Vb + (size_t)kr*DH + kc);

    for (int kt = 0; kt <= ktmax; kt++) {
        int kbase = kt * 32;
        *(uint4*)&Ks[kr][kc] = kreg;
        *(uint4*)&Vs[kr][kc] = vreg;
        __syncthreads();
        if (kt < ktmax) {   // prefetch next tile while computing this one
            kreg = *(const uint4*)(Kb + (size_t)(kbase + 32 + kr)*DH + kc);
            vreg = *(const uint4*)(Vb + (size_t)(kbase + 32 + kr)*DH + kc);
        }

        // --- S = Q K^T : warp tile (wm, wn) of 64x32 ---
        {
            wmma::fragment<wmma::accumulator, 16, 16, 16, float> s;
            wmma::fill_fragment(s, 0.0f);
            #pragma unroll
            for (int kk = 0; kk < 64; kk += 16) {
                wmma::fragment<wmma::matrix_a, 16, 16, 16, __nv_bfloat16, wmma::row_major> a;
                wmma::fragment<wmma::matrix_b, 16, 16, 16, __nv_bfloat16, wmma::col_major> b;
                wmma::load_matrix_sync(a, &Qs[wm*16][kk], 72);
                wmma::load_matrix_sync(b, &Ks[wn*16][kk], 72);
                wmma::mma_sync(s, a, b, s);
            }
            wmma::store_matrix_sync(&Ps[wm*16][wn*16], s, 36, wmma::mem_row_major);
        }
        __syncthreads();

        // --- P = exp(mask(S/8)) -> fp16; accumulate row sums ---
        {
            float psum = 0.0f;
            #pragma unroll
            for (int j = 0; j < 8; j++) {
                int col = pc0 + j;
                float p = __expf(Ps[prow][col] * 0.125f);
                if (kbase + col > qbase + prow) p = 0.0f;
                Pf[prow][col] = __float2half_rn(p);
                psum += p;
            }
            l_part += psum;
        }
        __syncthreads();

        // --- O += P V : warp rows wm*16, cols wn*32 + {0,16} ---
        #pragma unroll
        for (int kk = 0; kk < 32; kk += 16) {
            wmma::fragment<wmma::matrix_a, 16, 16, 16, __half, wmma::row_major> a;
            wmma::fragment<wmma::matrix_b, 16, 16, 16, __half, wmma::row_major> b0, b1;
            wmma::load_matrix_sync(a, &Pf[wm*16][kk], 40);
            wmma::load_matrix_sync(b0, &Vs[kk][wn*32], 72);
            wmma::load_matrix_sync(b1, &Vs[kk][wn*32 + 16], 72);
            wmma::mma_sync(oacc[0], a, b0, oacc[0]);
            wmma::mma_sync(oacc[1], a, b1, oacc[1]);
        }
        __syncthreads();   // protect Ks/Vs/Pf before next iter overwrites
    }

    // --- epilogue: unnormalized O straight to gmem; 1/l to g_L ---
    int b_ = bh / HH, h = bh % HH;
    float* obase = g_Vh + ((size_t)(b_*NN + qbase + wm*16))*DM + h*DH + wn*32;
    wmma::store_matrix_sync(obase,      oacc[0], DM, wmma::mem_row_major);
    wmma::store_matrix_sync(obase + 16, oacc[1], DM, wmma::mem_row_major);

    float l = l_part;
    l += __shfl_xor_sync(0xffffffffu, l, 1);
    l += __shfl_xor_sync(0xffffffffu, l, 2);
    if ((tid & 3) == 0)
        g_L[bh*NN + qbase + prow] = 1.0f / l;
}

// ---------------------------------------------------------------------------
extern "C" void kernel_launch(void* const* d_in, const int* in_sizes, int n_in,
                              void* d_out, int out_size) {
    const float* X  = (const float*)d_in[0];
    const float* Wq = (const float*)d_in[1];
    const float* Wk = (const float*)d_in[2];
    const float* Wv = (const float*)d_in[3];
    const float* Wo = (const float*)d_in[4];
    const float* bo = (const float*)d_in[5];
    float* out = (float*)d_out;

    dim3 ggrid(DM/TN, MROWS/TM);   // (8, 32)
    gemm_tf32<1><<<ggrid, 256>>>(X, Wq, nullptr, nullptr, 0);
    gemm_tf32<1><<<ggrid, 256>>>(X, Wk, nullptr, nullptr, 1);
    gemm_tf32<1><<<ggrid, 256>>>(X, Wv, nullptr, nullptr, 2);

    int rows = BB*HH*NN;                       // 65536
    int nblk = (rows*32 + 255) / 256;          // 8192
    l2norm_cvt<<<nblk, 256>>>(0, rows);
    l2norm_cvt<<<nblk, 256>>>(1, rows);
    vcvt<<<(MROWS*DM/4 + 255)/256, 256>>>();

    flash<<<dim3(NN/64, BB*HH), 256>>>();

    gemm_tf32<0><<<ggrid, 256>>>(nullptr, Wo, bo, out, 0);
}

// round 8
// speedup vs baseline: 2.3559x; 1.0847x over previous
#include <cuda_runtime.h>
#include <cstdint>
#include <math.h>
#include <mma.h>
#include <cuda_bf16.h>
#include <cuda_fp16.h>

using namespace nvcuda;

#define BB 2
#define NN 2048
#define DM 1024
#define HH 16
#define DH 64
#define MROWS (BB*NN)

// Scratch (device globals -- no allocations allowed)
__device__ float g_Q [MROWS*DM];           // fp32 [b,h,n,d] head-major
__device__ float g_K [MROWS*DM];
__device__ float g_V [MROWS*DM];
__device__ float g_Vh[MROWS*DM];           // O: unnorm fp32 -> tf32-normed by vh_norm
__device__ float g_Xc[MROWS*DM];           // X pre-converted to tf32 bits
__device__ float g_Wc[4*DM*DM];            // Wq,Wk,Wv,Wo pre-converted to tf32 bits
__device__ __nv_bfloat16 g_Qb[MROWS*DM];   // normalized Q, bf16
__device__ __nv_bfloat16 g_Kb[MROWS*DM];   // normalized K, bf16
__device__ __half        g_Vx[MROWS*DM];   // V, fp16
__device__ float g_L[BB*HH*NN];            // 1/l per (b,h,q)

__device__ __forceinline__ float* qkv_buf(int which) {
    return which == 0 ? g_Q : (which == 1 ? g_K : g_V);
}

// ---------------------------------------------------------------------------
// cp.async helpers
// ---------------------------------------------------------------------------
__device__ __forceinline__ void cp16(void* sdst, const void* gsrc) {
    unsigned int s = (unsigned int)__cvta_generic_to_shared(sdst);
    asm volatile("cp.async.cg.shared.global [%0], [%1], 16;\n" :: "r"(s), "l"(gsrc));
}
#define CP_COMMIT() asm volatile("cp.async.commit_group;\n" ::: "memory")

// ---------------------------------------------------------------------------
// fp32 -> tf32-bits conversion prepass (RN rounding preserved).
// dst_sel: 0 -> g_Xc, 1..4 -> g_Wc + (sel-1)*DM*DM
// ---------------------------------------------------------------------------
__global__ void cvt_tf32(const float* __restrict__ src, int dst_sel) {
    float* dst = (dst_sel == 0) ? g_Xc : (g_Wc + (size_t)(dst_sel - 1)*DM*DM);
    int i = blockIdx.x * blockDim.x + threadIdx.x;     // float4 index
    float4 v = ((const float4*)src)[i];
    float4 o;
    o.x = wmma::__float_to_tf32(v.x);
    o.y = wmma::__float_to_tf32(v.y);
    o.z = wmma::__float_to_tf32(v.z);
    o.w = wmma::__float_to_tf32(v.w);
    ((float4*)dst)[i] = o;
}

// ---------------------------------------------------------------------------
// Pipelined tf32 GEMM: C[M,1024] = A * W (+bias), 128x128x32 tiles,
// 2-stage cp.async double buffering, 256 threads. Operands hold tf32 bits.
// MODE 1: A = g_Xc, W = g_Wc[widx], head-major fp32 scatter into qkv_buf(which)
// MODE 0: A = g_Vh, W = g_Wc[3],   row-major out + bias (seeded into acc)
// Dynamic smem: As[2][128][36] | Ws[2][32][132] | Bs[16][132]  (~79 KB)
// ---------------------------------------------------------------------------
#define TM 128
#define TN 128
#define TK 32
#define A_ST 4608      // 128*36 floats per A stage
#define W_ST 4224      // 32*132 floats per W stage
#define SM_BIAS (2*A_ST + 2*W_ST)
#define SM_TOTAL_F (SM_BIAS + 16*132)

template<int MODE>
__global__ void gemm_tf32(const float* __restrict__ bias,
                          float* __restrict__ outp, int which) {
    const float* A = (MODE == 0) ? g_Vh : g_Xc;
    const float* W = g_Wc + (size_t)((MODE == 0) ? 3 : which)*DM*DM;
    extern __shared__ float dyn[];
    float* Asm = dyn;                    // [2][128][36]
    float* Wsm = dyn + 2*A_ST;           // [2][32][132]
    float* Bsm = dyn + SM_BIAS;          // [16][132]

    int tid  = threadIdx.x;
    int warp = tid >> 5;
    int wm   = warp >> 2;                // 0..1
    int wn   = warp & 3;                 // 0..3
    int bm = blockIdx.y * TM, bn = blockIdx.x * TN;

    wmma::fragment<wmma::accumulator, 16, 16, 8, float> acc[4][2];

    if (MODE == 0) {
        for (int idx = tid; idx < 16 * TN; idx += 256) {
            int r = idx >> 7, c = idx & 127;
            Bsm[r*132 + c] = bias[bn + c];
        }
        __syncthreads();
        #pragma unroll
        for (int i = 0; i < 4; i++)
            #pragma unroll
            for (int j = 0; j < 2; j++)
                wmma::load_matrix_sync(acc[i][j], &Bsm[wn*32 + j*16],
                                       132, wmma::mem_row_major);
        __syncthreads();
    } else {
        #pragma unroll
        for (int i = 0; i < 4; i++)
            #pragma unroll
            for (int j = 0; j < 2; j++)
                wmma::fill_fragment(acc[i][j], 0.0f);
    }

    // per-thread copy coords
    int ar = tid >> 3, ac = (tid & 7) * 4;    // A: 32 rows/pass
    int wr = tid >> 5, wc = (tid & 31) * 4;   // W: 8 rows/pass

    auto issue = [&](int k0, int s) {
        float* As = Asm + s*A_ST;
        float* Ws = Wsm + s*W_ST;
        #pragma unroll
        for (int i = 0; i < 4; i++) {
            int r = ar + i*32;
            cp16(&As[r*36 + ac], &A[(size_t)(bm + r)*DM + k0 + ac]);
        }
        #pragma unroll
        for (int i = 0; i < 4; i++) {
            int r = wr + i*8;
            cp16(&Ws[r*132 + wc], &W[(size_t)(k0 + r)*DM + bn + wc]);
        }
    };

    issue(0, 0);
    CP_COMMIT();

    const int NT = DM / TK;             // 32 k-tiles
    for (int t = 0; t < NT; t++) {
        int s = t & 1;
        if (t + 1 < NT) {
            issue((t+1)*TK, s ^ 1);
            CP_COMMIT();
            asm volatile("cp.async.wait_group 1;\n" ::: "memory");
        } else {
            asm volatile("cp.async.wait_group 0;\n" ::: "memory");
        }
        __syncthreads();

        float* As = Asm + s*A_ST;
        float* Ws = Wsm + s*W_ST;
        #pragma unroll
        for (int kk = 0; kk < TK; kk += 8) {
            wmma::fragment<wmma::matrix_a, 16, 16, 8, wmma::precision::tf32, wmma::row_major> af[4];
            wmma::fragment<wmma::matrix_b, 16, 16, 8, wmma::precision::tf32, wmma::row_major> bf[2];
            #pragma unroll
            for (int i = 0; i < 4; i++)
                wmma::load_matrix_sync(af[i], &As[(wm*64 + i*16)*36 + kk], 36);
            #pragma unroll
            for (int j = 0; j < 2; j++)
                wmma::load_matrix_sync(bf[j], &Ws[kk*132 + wn*32 + j*16], 132);
            #pragma unroll
            for (int i = 0; i < 4; i++)
                #pragma unroll
                for (int j = 0; j < 2; j++)
                    wmma::mma_sync(acc[i][j], af[i], bf[j], acc[i][j]);
        }
        __syncthreads();
    }

    if (MODE == 0) {
        #pragma unroll
        for (int i = 0; i < 4; i++)
            #pragma unroll
            for (int j = 0; j < 2; j++)
                wmma::store_matrix_sync(
                    &outp[(size_t)(bm + wm*64 + i*16)*DM + bn + wn*32 + j*16],
                    acc[i][j], DM, wmma::mem_row_major);
    } else {
        float* out = qkv_buf(which);
        #pragma unroll
        for (int i = 0; i < 4; i++) {
            int m = bm + wm*64 + i*16;
            int b_ = m / NN, n = m % NN;
            #pragma unroll
            for (int j = 0; j < 2; j++) {
                int c = bn + wn*32 + j*16;
                int h = c >> 6, d = c & 63;
                float* p = out + (((size_t)(b_*HH + h))*NN + n)*DH + d;
                wmma::store_matrix_sync(p, acc[i][j], DH, wmma::mem_row_major);
            }
        }
    }
}

// ---------------------------------------------------------------------------
// L2 normalize rows of 64 and convert to bf16. One warp per row.
// ---------------------------------------------------------------------------
__global__ void l2norm_cvt(int which, int rows) {
    const float* P = (which == 0) ? g_Q : g_K;
    __nv_bfloat16* O = (which == 0) ? g_Qb : g_Kb;
    int warp = (blockIdx.x * blockDim.x + threadIdx.x) >> 5;
    int lane = threadIdx.x & 31;
    if (warp >= rows) return;
    const float* p = P + (size_t)warp * DH;
    float x0 = p[lane], x1 = p[lane + 32];
    float ss = x0*x0 + x1*x1;
    #pragma unroll
    for (int o = 16; o; o >>= 1) ss += __shfl_xor_sync(0xffffffffu, ss, o);
    float inv = 1.0f / (sqrtf(ss) + 1e-6f);
    __nv_bfloat16* q = O + (size_t)warp * DH;
    q[lane]      = __float2bfloat16(x0 * inv);
    q[lane + 32] = __float2bfloat16(x1 * inv);
}

// V fp32 -> fp16
__global__ void vcvt() {
    int i = blockIdx.x * blockDim.x + threadIdx.x;
    const float4* src = (const float4*)g_V;
    __half2* dst = (__half2*)g_Vx;
    float4 v = src[i];
    dst[2*i]   = __floats2half2_rn(v.x, v.y);
    dst[2*i+1] = __floats2half2_rn(v.z, v.w);
}

// Normalize g_Vh by g_L and round to tf32 bits (so output GEMM can cp.async raw)
__global__ void vh_norm() {
    int i = blockIdx.x * blockDim.x + threadIdx.x;   // float4 index
    int flat = i * 4;
    int m = flat >> 10;
    int c = flat & 1023;
    int b_ = m >> 11, n = m & (NN-1);
    int h = c >> 6;
    float sc = g_L[(b_*HH + h)*NN + n];
    float4 v = ((const float4*)g_Vh)[i];
    v.x = wmma::__float_to_tf32(v.x * sc);
    v.y = wmma::__float_to_tf32(v.y * sc);
    v.z = wmma::__float_to_tf32(v.z * sc);
    v.w = wmma::__float_to_tf32(v.w * sc);
    ((float4*)g_Vh)[i] = v;
}

// ---------------------------------------------------------------------------
// Causal attention, bf16 (S) + fp16 (PV) tensor cores.
// Unit-norm Q,K => scores in [-0.125,0.125]: no running max, no rescale.
// ---------------------------------------------------------------------------
__global__ void flash() {
    __shared__ __nv_bfloat16 Qs[64][72];
    __shared__ __nv_bfloat16 Ks[32][72];
    __shared__ __half        Vs[32][72];
    __shared__ float         Ps[64][36];
    __shared__ __half        Pf[64][40];

    int tid = threadIdx.x;
    int warp = tid >> 5;
    int wm = warp >> 1, wn = warp & 1;
    int qt = blockIdx.x, bh = blockIdx.y;
    int qbase = qt * 64;
    const __nv_bfloat16* Qb = g_Qb + (size_t)bh * NN * DH;
    const __nv_bfloat16* Kb = g_Kb + (size_t)bh * NN * DH;
    const __half*        Vb = g_Vx + (size_t)bh * NN * DH;

    {
        int r = tid >> 2, c0 = (tid & 3) * 16;
        const uint4* s = (const uint4*)(Qb + (size_t)(qbase + r)*DH + c0);
        *(uint4*)&Qs[r][c0]     = s[0];
        *(uint4*)&Qs[r][c0 + 8] = s[1];
    }

    wmma::fragment<wmma::accumulator, 16, 16, 16, float> oacc[2];
    wmma::fill_fragment(oacc[0], 0.0f);
    wmma::fill_fragment(oacc[1], 0.0f);

    float l_part = 0.0f;
    int prow = tid >> 2;
    int pc0  = (tid & 3) * 8;

    int kr = tid >> 3, kc = (tid & 7) * 8;
    int ktmax = 2*qt + 1;
    uint4 kreg = *(const uint4*)(Kb + (size_t)kr*DH + kc);
    uint4 vreg = *(const uint4*)(Vb + (size_t)kr*DH + kc);

    for (int kt = 0; kt <= ktmax; kt++) {
        int kbase = kt * 32;
        *(uint4*)&Ks[kr][kc] = kreg;
        *(uint4*)&Vs[kr][kc] = vreg;
        __syncthreads();
        if (kt < ktmax) {
            kreg = *(const uint4*)(Kb + (size_t)(kbase + 32 + kr)*DH + kc);
            vreg = *(const uint4*)(Vb + (size_t)(kbase + 32 + kr)*DH + kc);
        }

        {
            wmma::fragment<wmma::accumulator, 16, 16, 16, float> s;
            wmma::fill_fragment(s, 0.0f);
            #pragma unroll
            for (int kk = 0; kk < 64; kk += 16) {
                wmma::fragment<wmma::matrix_a, 16, 16, 16, __nv_bfloat16, wmma::row_major> a;
                wmma::fragment<wmma::matrix_b, 16, 16, 16, __nv_bfloat16, wmma::col_major> b;
                wmma::load_matrix_sync(a, &Qs[wm*16][kk], 72);
                wmma::load_matrix_sync(b, &Ks[wn*16][kk], 72);
                wmma::mma_sync(s, a, b, s);
            }
            wmma::store_matrix_sync(&Ps[wm*16][wn*16], s, 36, wmma::mem_row_major);
        }
        __syncthreads();

        {
            float psum = 0.0f;
            #pragma unroll
            for (int j = 0; j < 8; j++) {
                int col = pc0 + j;
                float p = __expf(Ps[prow][col] * 0.125f);
                if (kbase + col > qbase + prow) p = 0.0f;
                Pf[prow][col] = __float2half_rn(p);
                psum += p;
            }
            l_part += psum;
        }
        __syncthreads();

        #pragma unroll
        for (int kk = 0; kk < 32; kk += 16) {
            wmma::fragment<wmma::matrix_a, 16, 16, 16, __half, wmma::row_major> a;
            wmma::fragment<wmma::matrix_b, 16, 16, 16, __half, wmma::row_major> b0, b1;
            wmma::load_matrix_sync(a, &Pf[wm*16][kk], 40);
            wmma::load_matrix_sync(b0, &Vs[kk][wn*32], 72);
            wmma::load_matrix_sync(b1, &Vs[kk][wn*32 + 16], 72);
            wmma::mma_sync(oacc[0], a, b0, oacc[0]);
            wmma::mma_sync(oacc[1], a, b1, oacc[1]);
        }
        __syncthreads();
    }

    int b_ = bh / HH, h = bh % HH;
    float* obase = g_Vh + ((size_t)(b_*NN + qbase + wm*16))*DM + h*DH + wn*32;
    wmma::store_matrix_sync(obase,      oacc[0], DM, wmma::mem_row_major);
    wmma::store_matrix_sync(obase + 16, oacc[1], DM, wmma::mem_row_major);

    float l = l_part;
    l += __shfl_xor_sync(0xffffffffu, l, 1);
    l += __shfl_xor_sync(0xffffffffu, l, 2);
    if ((tid & 3) == 0)
        g_L[bh*NN + qbase + prow] = 1.0f / l;
}

// ---------------------------------------------------------------------------
extern "C" void kernel_launch(void* const* d_in, const int* in_sizes, int n_in,
                              void* d_out, int out_size) {
    const float* X  = (const float*)d_in[0];
    const float* Wq = (const float*)d_in[1];
    const float* Wk = (const float*)d_in[2];
    const float* Wv = (const float*)d_in[3];
    const float* Wo = (const float*)d_in[4];
    const float* bo = (const float*)d_in[5];
    float* out = (float*)d_out;

    size_t dynbytes = SM_TOTAL_F * sizeof(float);   // ~79 KB
    cudaFuncSetAttribute(gemm_tf32<0>, cudaFuncAttributeMaxDynamicSharedMemorySize, (int)dynbytes);
    cudaFuncSetAttribute(gemm_tf32<1>, cudaFuncAttributeMaxDynamicSharedMemorySize, (int)dynbytes);

    // prepass: convert X and weights to tf32 bits (RN)
    cvt_tf32<<<MROWS*DM/4/256, 256>>>(X,  0);
    cvt_tf32<<<DM*DM/4/256, 256>>>(Wq, 1);
    cvt_tf32<<<DM*DM/4/256, 256>>>(Wk, 2);
    cvt_tf32<<<DM*DM/4/256, 256>>>(Wv, 3);
    cvt_tf32<<<DM*DM/4/256, 256>>>(Wo, 4);

    dim3 ggrid(DM/TN, MROWS/TM);   // (8, 32)
    gemm_tf32<1><<<ggrid, 256, dynbytes>>>(nullptr, nullptr, 0);
    gemm_tf32<1><<<ggrid, 256, dynbytes>>>(nullptr, nullptr, 1);
    gemm_tf32<1><<<ggrid, 256, dynbytes>>>(nullptr, nullptr, 2);

    int rows = BB*HH*NN;
    int nblk = (rows*32 + 255) / 256;
    l2norm_cvt<<<nblk, 256>>>(0, rows);
    l2norm_cvt<<<nblk, 256>>>(1, rows);
    vcvt<<<(MROWS*DM/4 + 255)/256, 256>>>();

    flash<<<dim3(NN/64, BB*HH), 256>>>();

    vh_norm<<<(MROWS*DM/4 + 255)/256, 256>>>();

    gemm_tf32<0><<<ggrid, 256, dynbytes>>>(bo, out, 0);
}

// round 9
// speedup vs baseline: 5.0718x; 2.1527x over previous
#include <cuda_runtime.h>
#include <cstdint>
#include <math.h>
#include <mma.h>
#include <cuda_bf16.h>
#include <cuda_fp16.h>

using namespace nvcuda;

#define BB 2
#define NN 2048
#define DM 1024
#define HH 16
#define DH 64
#define MROWS (BB*NN)

// Scratch (device globals -- no allocations allowed)
__device__ float g_Q [MROWS*DM];           // fp32 [b,h,n,d] head-major
__device__ float g_K [MROWS*DM];
__device__ float g_V [MROWS*DM];
__device__ float g_Vh[MROWS*DM];           // O: unnormalized fp32
__device__ __half g_Xh[MROWS*DM];          // X in fp16
__device__ __half g_Wh[4*DM*DM];           // Wq,Wk,Wv,Wo in fp16
__device__ __half g_Vhh[MROWS*DM];         // normalized O in fp16
__device__ __nv_bfloat16 g_Qb[MROWS*DM];   // normalized Q, bf16
__device__ __nv_bfloat16 g_Kb[MROWS*DM];   // normalized K, bf16
__device__ __half        g_Vx[MROWS*DM];   // V, fp16
__device__ float g_L[BB*HH*NN];            // 1/l per (b,h,q)

__device__ __forceinline__ float* qkv_buf(int which) {
    return which == 0 ? g_Q : (which == 1 ? g_K : g_V);
}

// ---------------------------------------------------------------------------
// cp.async helpers
// ---------------------------------------------------------------------------
__device__ __forceinline__ void cp16(void* sdst, const void* gsrc) {
    unsigned int s = (unsigned int)__cvta_generic_to_shared(sdst);
    asm volatile("cp.async.cg.shared.global [%0], [%1], 16;\n" :: "r"(s), "l"(gsrc));
}
#define CP_COMMIT() asm volatile("cp.async.commit_group;\n" ::: "memory")

// ---------------------------------------------------------------------------
// fp32 -> fp16 prepasses.  Each thread converts 8 floats -> 8 halves (16B out).
// ---------------------------------------------------------------------------
__global__ void cvt_x(const float* __restrict__ src) {
    int i = blockIdx.x * blockDim.x + threadIdx.x;     // 8-elem group
    float4 a = ((const float4*)src)[2*i];
    float4 b = ((const float4*)src)[2*i+1];
    __half2 o[4] = { __floats2half2_rn(a.x, a.y), __floats2half2_rn(a.z, a.w),
                     __floats2half2_rn(b.x, b.y), __floats2half2_rn(b.z, b.w) };
    ((uint4*)g_Xh)[i] = *(uint4*)o;
}

__global__ void cvt_w(const float* __restrict__ w0, const float* __restrict__ w1,
                      const float* __restrict__ w2, const float* __restrict__ w3) {
    int i = blockIdx.x * blockDim.x + threadIdx.x;     // 8-elem group over 4M elems
    const int per = DM*DM/8;
    int which = i / per, r = i % per;
    const float* src = which == 0 ? w0 : which == 1 ? w1 : which == 2 ? w2 : w3;
    float4 a = ((const float4*)src)[2*r];
    float4 b = ((const float4*)src)[2*r+1];
    __half2 o[4] = { __floats2half2_rn(a.x, a.y), __floats2half2_rn(a.z, a.w),
                     __floats2half2_rn(b.x, b.y), __floats2half2_rn(b.z, b.w) };
    ((uint4*)g_Wh)[i] = *(uint4*)o;
}

// ---------------------------------------------------------------------------
// Pipelined fp16 GEMM: C[M,1024] = A * W (+bias), 128x128x32 tiles,
// 3-stage cp.async, 256 threads, m16n16k16 HMMA, fp32 accumulate.
// MODE 1: A = g_Xh, W = g_Wh[which], head-major fp32 scatter into qkv_buf
// MODE 0: A = g_Vhh, W = g_Wh[3],   row-major out + bias (seeded into acc)
// Dyn smem: A[3][128][40]h | W[3][32][136]h | Bias[16][132]f  (~64 KB)
// ---------------------------------------------------------------------------
#define TM 128
#define TN 128
#define TK 32
#define NSTAGE 3
#define A_ST (128*40)       // halves
#define W_ST (32*136)       // halves
#define SM_HALVES (NSTAGE*(A_ST + W_ST))
#define SM_BYTES (SM_HALVES*2 + 16*132*4)

template<int MODE>
__global__ void gemm_h(const float* __restrict__ bias,
                       float* __restrict__ outp, int which) {
    const __half* A = (MODE == 0) ? g_Vhh : g_Xh;
    const __half* W = g_Wh + (size_t)((MODE == 0) ? 3 : which)*DM*DM;
    extern __shared__ __align__(16) char dync[];
    __half* Ah = (__half*)dync;
    __half* Wh = Ah + NSTAGE*A_ST;
    float*  Bs = (float*)(Wh + NSTAGE*W_ST);

    int tid  = threadIdx.x;
    int warp = tid >> 5;
    int wm   = warp >> 2;                // 0..1
    int wn   = warp & 3;                 // 0..3
    int bm = blockIdx.y * TM, bn = blockIdx.x * TN;

    wmma::fragment<wmma::accumulator, 16, 16, 16, float> acc[4][2];

    if (MODE == 0) {
        for (int idx = tid; idx < 16 * TN; idx += 256) {
            int r = idx >> 7, c = idx & 127;
            Bs[r*132 + c] = bias[bn + c];
        }
        __syncthreads();
        #pragma unroll
        for (int i = 0; i < 4; i++)
            #pragma unroll
            for (int j = 0; j < 2; j++)
                wmma::load_matrix_sync(acc[i][j], &Bs[wn*32 + j*16],
                                       132, wmma::mem_row_major);
        __syncthreads();
    } else {
        #pragma unroll
        for (int i = 0; i < 4; i++)
            #pragma unroll
            for (int j = 0; j < 2; j++)
                wmma::fill_fragment(acc[i][j], 0.0f);
    }

    // copy mapping: A 128r x 4 chunks(8h); W 32r x 16 chunks(8h); 2 passes each
    int aro = tid >> 2, aco = (tid & 3) * 8;
    int wro = tid >> 4, wco = (tid & 15) * 8;

    auto issue = [&](int t) {
        int s = t % NSTAGE;
        int k0 = t * TK;
        __half* As = Ah + s*A_ST;
        __half* Ws = Wh + s*W_ST;
        #pragma unroll
        for (int p = 0; p < 2; p++) {
            int r = aro + p*64;
            cp16(&As[r*40 + aco], &A[(size_t)(bm + r)*DM + k0 + aco]);
        }
        #pragma unroll
        for (int p = 0; p < 2; p++) {
            int r = wro + p*16;
            cp16(&Ws[r*136 + wco], &W[(size_t)(k0 + r)*DM + bn + wco]);
        }
        CP_COMMIT();
    };

    issue(0);
    issue(1);

    const int NT = DM / TK;             // 32 k-tiles
    for (int t = 0; t < NT; t++) {
        if (t + 1 < NT)
            asm volatile("cp.async.wait_group 1;\n" ::: "memory");
        else
            asm volatile("cp.async.wait_group 0;\n" ::: "memory");
        __syncthreads();
        if (t + 2 < NT) issue(t + 2);   // stage (t+2)%3 free: consumed at t-1

        int s = t % NSTAGE;
        __half* As = Ah + s*A_ST;
        __half* Ws = Wh + s*W_ST;
        #pragma unroll
        for (int kk = 0; kk < TK; kk += 16) {
            wmma::fragment<wmma::matrix_a, 16, 16, 16, __half, wmma::row_major> af[4];
            wmma::fragment<wmma::matrix_b, 16, 16, 16, __half, wmma::row_major> bf[2];
            #pragma unroll
            for (int i = 0; i < 4; i++)
                wmma::load_matrix_sync(af[i], &As[(wm*64 + i*16)*40 + kk], 40);
            #pragma unroll
            for (int j = 0; j < 2; j++)
                wmma::load_matrix_sync(bf[j], &Ws[kk*136 + wn*32 + j*16], 136);
            #pragma unroll
            for (int i = 0; i < 4; i++)
                #pragma unroll
                for (int j = 0; j < 2; j++)
                    wmma::mma_sync(acc[i][j], af[i], bf[j], acc[i][j]);
        }
        __syncthreads();
    }

    if (MODE == 0) {
        #pragma unroll
        for (int i = 0; i < 4; i++)
            #pragma unroll
            for (int j = 0; j < 2; j++)
                wmma::store_matrix_sync(
                    &outp[(size_t)(bm + wm*64 + i*16)*DM + bn + wn*32 + j*16],
                    acc[i][j], DM, wmma::mem_row_major);
    } else {
        float* out = qkv_buf(which);
        #pragma unroll
        for (int i = 0; i < 4; i++) {
            int m = bm + wm*64 + i*16;
            int b_ = m / NN, n = m % NN;
            #pragma unroll
            for (int j = 0; j < 2; j++) {
                int c = bn + wn*32 + j*16;
                int h = c >> 6, d = c & 63;
                float* p = out + (((size_t)(b_*HH + h))*NN + n)*DH + d;
                wmma::store_matrix_sync(p, acc[i][j], DH, wmma::mem_row_major);
            }
        }
    }
}

// ---------------------------------------------------------------------------
// L2 normalize rows of 64 and convert to bf16. One warp per row.
// ---------------------------------------------------------------------------
__global__ void l2norm_cvt(int which, int rows) {
    const float* P = (which == 0) ? g_Q : g_K;
    __nv_bfloat16* O = (which == 0) ? g_Qb : g_Kb;
    int warp = (blockIdx.x * blockDim.x + threadIdx.x) >> 5;
    int lane = threadIdx.x & 31;
    if (warp >= rows) return;
    const float* p = P + (size_t)warp * DH;
    float x0 = p[lane], x1 = p[lane + 32];
    float ss = x0*x0 + x1*x1;
    #pragma unroll
    for (int o = 16; o; o >>= 1) ss += __shfl_xor_sync(0xffffffffu, ss, o);
    float inv = 1.0f / (sqrtf(ss) + 1e-6f);
    __nv_bfloat16* q = O + (size_t)warp * DH;
    q[lane]      = __float2bfloat16(x0 * inv);
    q[lane + 32] = __float2bfloat16(x1 * inv);
}

// V fp32 -> fp16
__global__ void vcvt() {
    int i = blockIdx.x * blockDim.x + threadIdx.x;
    const float4* src = (const float4*)g_V;
    __half2* dst = (__half2*)g_Vx;
    float4 v = src[i];
    dst[2*i]   = __floats2half2_rn(v.x, v.y);
    dst[2*i+1] = __floats2half2_rn(v.z, v.w);
}

// Normalize g_Vh by g_L -> fp16 g_Vhh (A operand of output GEMM)
__global__ void vh_norm() {
    int i = blockIdx.x * blockDim.x + threadIdx.x;   // 8-elem group
    int flat = i * 8;
    int m = flat >> 10;
    int c = flat & 1023;
    int b_ = m >> 11, n = m & (NN-1);
    int h = c >> 6;
    float sc = g_L[(b_*HH + h)*NN + n];
    float4 a = ((const float4*)g_Vh)[2*i];
    float4 b = ((const float4*)g_Vh)[2*i+1];
    __half2 o[4] = { __floats2half2_rn(a.x*sc, a.y*sc), __floats2half2_rn(a.z*sc, a.w*sc),
                     __floats2half2_rn(b.x*sc, b.y*sc), __floats2half2_rn(b.z*sc, b.w*sc) };
    ((uint4*)g_Vhh)[i] = *(uint4*)o;
}

// ---------------------------------------------------------------------------
// Causal attention, bf16 (S) + fp16 (PV) tensor cores (unchanged).
// Unit-norm Q,K => scores in [-0.125,0.125]: no running max, no rescale.
// ---------------------------------------------------------------------------
__global__ void flash() {
    __shared__ __nv_bfloat16 Qs[64][72];
    __shared__ __nv_bfloat16 Ks[32][72];
    __shared__ __half        Vs[32][72];
    __shared__ float         Ps[64][36];
    __shared__ __half        Pf[64][40];

    int tid = threadIdx.x;
    int warp = tid >> 5;
    int wm = warp >> 1, wn = warp & 1;
    int qt = blockIdx.x, bh = blockIdx.y;
    int qbase = qt * 64;
    const __nv_bfloat16* Qb = g_Qb + (size_t)bh * NN * DH;
    const __nv_bfloat16* Kb = g_Kb + (size_t)bh * NN * DH;
    const __half*        Vb = g_Vx + (size_t)bh * NN * DH;

    {
        int r = tid >> 2, c0 = (tid & 3) * 16;
        const uint4* s = (const uint4*)(Qb + (size_t)(qbase + r)*DH + c0);
        *(uint4*)&Qs[r][c0]     = s[0];
        *(uint4*)&Qs[r][c0 + 8] = s[1];
    }

    wmma::fragment<wmma::accumulator, 16, 16, 16, float> oacc[2];
    wmma::fill_fragment(oacc[0], 0.0f);
    wmma::fill_fragment(oacc[1], 0.0f);

    float l_part = 0.0f;
    int prow = tid >> 2;
    int pc0  = (tid & 3) * 8;

    int kr = tid >> 3, kc = (tid & 7) * 8;
    int ktmax = 2*qt + 1;
    uint4 kreg = *(const uint4*)(Kb + (size_t)kr*DH + kc);
    uint4 vreg = *(const uint4*)(Vb + (size_t)kr*DH + kc);

    for (int kt = 0; kt <= ktmax; kt++) {
        int kbase = kt * 32;
        *(uint4*)&Ks[kr][kc] = kreg;
        *(uint4*)&Vs[kr][kc] = vreg;
        __syncthreads();
        if (kt < ktmax) {
            kreg = *(const uint4*)(Kb + (size_t)(kbase + 32 + kr)*DH + kc);
            vreg = *(const uint4*)(Vb + (size_t)(kbase + 32 + kr)*DH + kc);
        }

        {
            wmma::fragment<wmma::accumulator, 16, 16, 16, float> s;
            wmma::fill_fragment(s, 0.0f);
            #pragma unroll
            for (int kk = 0; kk < 64; kk += 16) {
                wmma::fragment<wmma::matrix_a, 16, 16, 16, __nv_bfloat16, wmma::row_major> a;
                wmma::fragment<wmma::matrix_b, 16, 16, 16, __nv_bfloat16, wmma::col_major> b;
                wmma::load_matrix_sync(a, &Qs[wm*16][kk], 72);
                wmma::load_matrix_sync(b, &Ks[wn*16][kk], 72);
                wmma::mma_sync(s, a, b, s);
            }
            wmma::store_matrix_sync(&Ps[wm*16][wn*16], s, 36, wmma::mem_row_major);
        }
        __syncthreads();

        {
            float psum = 0.0f;
            #pragma unroll
            for (int j = 0; j < 8; j++) {
                int col = pc0 + j;
                float p = __expf(Ps[prow][col] * 0.125f);
                if (kbase + col > qbase + prow) p = 0.0f;
                Pf[prow][col] = __float2half_rn(p);
                psum += p;
            }
            l_part += psum;
        }
        __syncthreads();

        #pragma unroll
        for (int kk = 0; kk < 32; kk += 16) {
            wmma::fragment<wmma::matrix_a, 16, 16, 16, __half, wmma::row_major> a;
            wmma::fragment<wmma::matrix_b, 16, 16, 16, __half, wmma::row_major> b0, b1;
            wmma::load_matrix_sync(a, &Pf[wm*16][kk], 40);
            wmma::load_matrix_sync(b0, &Vs[kk][wn*32], 72);
            wmma::load_matrix_sync(b1, &Vs[kk][wn*32 + 16], 72);
            wmma::mma_sync(oacc[0], a, b0, oacc[0]);
            wmma::mma_sync(oacc[1], a, b1, oacc[1]);
        }
        __syncthreads();
    }

    int b_ = bh / HH, h = bh % HH;
    float* obase = g_Vh + ((size_t)(b_*NN + qbase + wm*16))*DM + h*DH + wn*32;
    wmma::store_matrix_sync(obase,      oacc[0], DM, wmma::mem_row_major);
    wmma::store_matrix_sync(obase + 16, oacc[1], DM, wmma::mem_row_major);

    float l = l_part;
    l += __shfl_xor_sync(0xffffffffu, l, 1);
    l += __shfl_xor_sync(0xffffffffu, l, 2);
    if ((tid & 3) == 0)
        g_L[bh*NN + qbase + prow] = 1.0f / l;
}

// ---------------------------------------------------------------------------
extern "C" void kernel_launch(void* const* d_in, const int* in_sizes, int n_in,
                              void* d_out, int out_size) {
    const float* X  = (const float*)d_in[0];
    const float* Wq = (const float*)d_in[1];
    const float* Wk = (const float*)d_in[2];
    const float* Wv = (const float*)d_in[3];
    const float* Wo = (const float*)d_in[4];
    const float* bo = (const float*)d_in[5];
    float* out = (float*)d_out;

    cudaFuncSetAttribute(gemm_h<0>, cudaFuncAttributeMaxDynamicSharedMemorySize, SM_BYTES);
    cudaFuncSetAttribute(gemm_h<1>, cudaFuncAttributeMaxDynamicSharedMemorySize, SM_BYTES);

    // prepass: X and all weights -> fp16
    cvt_x<<<MROWS*DM/8/256, 256>>>(X);
    cvt_w<<<4*DM*DM/8/256, 256>>>(Wq, Wk, Wv, Wo);

    dim3 ggrid(DM/TN, MROWS/TM);   // (8, 32)
    gemm_h<1><<<ggrid, 256, SM_BYTES>>>(nullptr, nullptr, 0);
    gemm_h<1><<<ggrid, 256, SM_BYTES>>>(nullptr, nullptr, 1);
    gemm_h<1><<<ggrid, 256, SM_BYTES>>>(nullptr, nullptr, 2);

    int rows = BB*HH*NN;
    int nblk = (rows*32 + 255) / 256;
    l2norm_cvt<<<nblk, 256>>>(0, rows);
    l2norm_cvt<<<nblk, 256>>>(1, rows);
    vcvt<<<(MROWS*DM/4 + 255)/256, 256>>>();

    flash<<<dim3(NN/64, BB*HH), 256>>>();

    vh_norm<<<(MROWS*DM/8 + 255)/256, 256>>>();

    gemm_h<0><<<ggrid, 256, SM_BYTES>>>(bo, out, 0);
}

// round 10
// speedup vs baseline: 5.8888x; 1.1611x over previous
#include <cuda_runtime.h>
#include <cstdint>
#include <math.h>
#include <mma.h>
#include <cuda_bf16.h>
#include <cuda_fp16.h>

using namespace nvcuda;

#define BB 2
#define NN 2048
#define DM 1024
#define HH 16
#define DH 64
#define MROWS (BB*NN)

// Scratch (device globals -- no allocations allowed)
__device__ float g_Q [MROWS*DM];           // fp32 [b,h,n,d] head-major
__device__ float g_K [MROWS*DM];
__device__ float g_V [MROWS*DM];
__device__ float g_Vh[MROWS*DM];           // O: unnormalized fp32
__device__ __half g_Xh[MROWS*DM];          // X in fp16
__device__ __half g_Wh[4*DM*DM];           // Wq,Wk,Wv,Wo in fp16
__device__ __half g_Vhh[MROWS*DM];         // normalized O in fp16
__device__ __nv_bfloat16 g_Qb[MROWS*DM];   // normalized Q, bf16
__device__ __nv_bfloat16 g_Kb[MROWS*DM];   // normalized K, bf16
__device__ __half        g_Vx[MROWS*DM];   // V, fp16
__device__ float g_L[BB*HH*NN];            // 1/l per (b,h,q)

__device__ __forceinline__ float* qkv_buf(int which) {
    return which == 0 ? g_Q : (which == 1 ? g_K : g_V);
}

// ---------------------------------------------------------------------------
// cp.async helpers
// ---------------------------------------------------------------------------
__device__ __forceinline__ void cp16(void* sdst, const void* gsrc) {
    unsigned int s = (unsigned int)__cvta_generic_to_shared(sdst);
    asm volatile("cp.async.cg.shared.global [%0], [%1], 16;\n" :: "r"(s), "l"(gsrc));
}
#define CP_COMMIT() asm volatile("cp.async.commit_group;\n" ::: "memory")

// ---------------------------------------------------------------------------
// fp32 -> fp16 prepasses
// ---------------------------------------------------------------------------
__global__ void cvt_x(const float* __restrict__ src) {
    int i = blockIdx.x * blockDim.x + threadIdx.x;
    float4 a = ((const float4*)src)[2*i];
    float4 b = ((const float4*)src)[2*i+1];
    __half2 o[4] = { __floats2half2_rn(a.x, a.y), __floats2half2_rn(a.z, a.w),
                     __floats2half2_rn(b.x, b.y), __floats2half2_rn(b.z, b.w) };
    ((uint4*)g_Xh)[i] = *(uint4*)o;
}

__global__ void cvt_w(const float* __restrict__ w0, const float* __restrict__ w1,
                      const float* __restrict__ w2, const float* __restrict__ w3) {
    int i = blockIdx.x * blockDim.x + threadIdx.x;
    const int per = DM*DM/8;
    int which = i / per, r = i % per;
    const float* src = which == 0 ? w0 : which == 1 ? w1 : which == 2 ? w2 : w3;
    float4 a = ((const float4*)src)[2*r];
    float4 b = ((const float4*)src)[2*r+1];
    __half2 o[4] = { __floats2half2_rn(a.x, a.y), __floats2half2_rn(a.z, a.w),
                     __floats2half2_rn(b.x, b.y), __floats2half2_rn(b.z, b.w) };
    ((uint4*)g_Wh)[i] = *(uint4*)o;
}

// ---------------------------------------------------------------------------
// Pipelined fp16 GEMM: 128x128x32 tiles, 3-stage cp.async, 256 threads.
// MODE 1: A = g_Xh, W = g_Wh[blockIdx.z], head-major fp32 scatter (QKV fused)
// MODE 0: A = g_Vhh, W = g_Wh[3], row-major out + bias
// ---------------------------------------------------------------------------
#define TM 128
#define TN 128
#define TK 32
#define NSTAGE 3
#define A_ST (128*40)
#define W_ST (32*136)
#define SM_BYTES (NSTAGE*(A_ST + W_ST)*2 + 16*132*4)

template<int MODE>
__global__ void gemm_h(const float* __restrict__ bias,
                       float* __restrict__ outp) {
    const int which = (MODE == 1) ? blockIdx.z : 0;
    const __half* A = (MODE == 0) ? g_Vhh : g_Xh;
    const __half* W = g_Wh + (size_t)((MODE == 0) ? 3 : which)*DM*DM;
    extern __shared__ __align__(16) char dync[];
    __half* Ah = (__half*)dync;
    __half* Wh = Ah + NSTAGE*A_ST;
    float*  Bs = (float*)(Wh + NSTAGE*W_ST);

    int tid  = threadIdx.x;
    int warp = tid >> 5;
    int wm   = warp >> 2;
    int wn   = warp & 3;
    int bm = blockIdx.y * TM, bn = blockIdx.x * TN;

    wmma::fragment<wmma::accumulator, 16, 16, 16, float> acc[4][2];

    if (MODE == 0) {
        for (int idx = tid; idx < 16 * TN; idx += 256) {
            int r = idx >> 7, c = idx & 127;
            Bs[r*132 + c] = bias[bn + c];
        }
        __syncthreads();
        #pragma unroll
        for (int i = 0; i < 4; i++)
            #pragma unroll
            for (int j = 0; j < 2; j++)
                wmma::load_matrix_sync(acc[i][j], &Bs[wn*32 + j*16],
                                       132, wmma::mem_row_major);
        __syncthreads();
    } else {
        #pragma unroll
        for (int i = 0; i < 4; i++)
            #pragma unroll
            for (int j = 0; j < 2; j++)
                wmma::fill_fragment(acc[i][j], 0.0f);
    }

    int aro = tid >> 2, aco = (tid & 3) * 8;
    int wro = tid >> 4, wco = (tid & 15) * 8;

    auto issue = [&](int t) {
        int s = t % NSTAGE;
        int k0 = t * TK;
        __half* As = Ah + s*A_ST;
        __half* Ws = Wh + s*W_ST;
        #pragma unroll
        for (int p = 0; p < 2; p++) {
            int r = aro + p*64;
            cp16(&As[r*40 + aco], &A[(size_t)(bm + r)*DM + k0 + aco]);
        }
        #pragma unroll
        for (int p = 0; p < 2; p++) {
            int r = wro + p*16;
            cp16(&Ws[r*136 + wco], &W[(size_t)(k0 + r)*DM + bn + wco]);
        }
        CP_COMMIT();
    };

    issue(0);
    issue(1);

    const int NT = DM / TK;
    for (int t = 0; t < NT; t++) {
        if (t + 1 < NT)
            asm volatile("cp.async.wait_group 1;\n" ::: "memory");
        else
            asm volatile("cp.async.wait_group 0;\n" ::: "memory");
        __syncthreads();
        if (t + 2 < NT) issue(t + 2);

        int s = t % NSTAGE;
        __half* As = Ah + s*A_ST;
        __half* Ws = Wh + s*W_ST;
        #pragma unroll
        for (int kk = 0; kk < TK; kk += 16) {
            wmma::fragment<wmma::matrix_a, 16, 16, 16, __half, wmma::row_major> af[4];
            wmma::fragment<wmma::matrix_b, 16, 16, 16, __half, wmma::row_major> bf[2];
            #pragma unroll
            for (int i = 0; i < 4; i++)
                wmma::load_matrix_sync(af[i], &As[(wm*64 + i*16)*40 + kk], 40);
            #pragma unroll
            for (int j = 0; j < 2; j++)
                wmma::load_matrix_sync(bf[j], &Ws[kk*136 + wn*32 + j*16], 136);
            #pragma unroll
            for (int i = 0; i < 4; i++)
                #pragma unroll
                for (int j = 0; j < 2; j++)
                    wmma::mma_sync(acc[i][j], af[i], bf[j], acc[i][j]);
        }
        __syncthreads();
    }

    if (MODE == 0) {
        #pragma unroll
        for (int i = 0; i < 4; i++)
            #pragma unroll
            for (int j = 0; j < 2; j++)
                wmma::store_matrix_sync(
                    &outp[(size_t)(bm + wm*64 + i*16)*DM + bn + wn*32 + j*16],
                    acc[i][j], DM, wmma::mem_row_major);
    } else {
        float* out = qkv_buf(which);
        #pragma unroll
        for (int i = 0; i < 4; i++) {
            int m = bm + wm*64 + i*16;
            int b_ = m / NN, n = m % NN;
            #pragma unroll
            for (int j = 0; j < 2; j++) {
                int c = bn + wn*32 + j*16;
                int h = c >> 6, d = c & 63;
                float* p = out + (((size_t)(b_*HH + h))*NN + n)*DH + d;
                wmma::store_matrix_sync(p, acc[i][j], DH, wmma::mem_row_major);
            }
        }
    }
}

// ---------------------------------------------------------------------------
// L2 normalize rows of 64 -> bf16, Q and K in one launch. One warp per row.
// ---------------------------------------------------------------------------
__global__ void l2norm_cvt(int rows) {
    int gw = (blockIdx.x * blockDim.x + threadIdx.x) >> 5;
    int lane = threadIdx.x & 31;
    int which = gw >= rows;
    int row = which ? gw - rows : gw;
    const float* P = which ? g_K : g_Q;
    __nv_bfloat16* O = which ? g_Kb : g_Qb;
    const float* p = P + (size_t)row * DH;
    float x0 = p[lane], x1 = p[lane + 32];
    float ss = x0*x0 + x1*x1;
    #pragma unroll
    for (int o = 16; o; o >>= 1) ss += __shfl_xor_sync(0xffffffffu, ss, o);
    float inv = 1.0f / (sqrtf(ss) + 1e-6f);
    __nv_bfloat16* q = O + (size_t)row * DH;
    q[lane]      = __float2bfloat16(x0 * inv);
    q[lane + 32] = __float2bfloat16(x1 * inv);
}

// V fp32 -> fp16
__global__ void vcvt() {
    int i = blockIdx.x * blockDim.x + threadIdx.x;
    const float4* src = (const float4*)g_V;
    __half2* dst = (__half2*)g_Vx;
    float4 v = src[i];
    dst[2*i]   = __floats2half2_rn(v.x, v.y);
    dst[2*i+1] = __floats2half2_rn(v.z, v.w);
}

// Normalize g_Vh by g_L -> fp16 g_Vhh
__global__ void vh_norm() {
    int i = blockIdx.x * blockDim.x + threadIdx.x;
    int flat = i * 8;
    int m = flat >> 10;
    int c = flat & 1023;
    int b_ = m >> 11, n = m & (NN-1);
    int h = c >> 6;
    float sc = g_L[(b_*HH + h)*NN + n];
    float4 a = ((const float4*)g_Vh)[2*i];
    float4 b = ((const float4*)g_Vh)[2*i+1];
    __half2 o[4] = { __floats2half2_rn(a.x*sc, a.y*sc), __floats2half2_rn(a.z*sc, a.w*sc),
                     __floats2half2_rn(b.x*sc, b.y*sc), __floats2half2_rn(b.z*sc, b.w*sc) };
    ((uint4*)g_Vhh)[i] = *(uint4*)o;
}

// ---------------------------------------------------------------------------
// Causal attention, bf16 (S) + fp16 (PV). q-tile 128, k-tile 64, 256 thr.
// Unit-norm Q,K => scores in [-0.125,0.125]: no running max, no rescale.
// Warp w owns rows w*16..w*16+15 of S (128x64) and O (128x64).
// Dyn smem: Qs[128][72]bf | Ks[64][72]bf | Vs[64][72]h | Ps[128][68]f |
//           Pf[128][72]h   = 90112 B
// ---------------------------------------------------------------------------
#define BQ 128
#define BK 64
#define FL_QS 0
#define FL_KS 18432
#define FL_VS 27648
#define FL_PS 36864
#define FL_PF 71680
#define FL_BYTES 90112

__global__ void flash() {
    extern __shared__ __align__(16) char fsm[];
    __nv_bfloat16* Qs = (__nv_bfloat16*)(fsm + FL_QS);
    __nv_bfloat16* Ks = (__nv_bfloat16*)(fsm + FL_KS);
    __half*        Vs = (__half*)(fsm + FL_VS);
    float*         Ps = (float*)(fsm + FL_PS);
    __half*        Pf = (__half*)(fsm + FL_PF);

    int tid = threadIdx.x;
    int w = tid >> 5;
    int qt = blockIdx.x, bh = blockIdx.y;
    int qbase = qt * BQ;
    const __nv_bfloat16* Qb = g_Qb + (size_t)bh * NN * DH;
    const __nv_bfloat16* Kb = g_Kb + (size_t)bh * NN * DH;
    const __half*        Vb = g_Vx + (size_t)bh * NN * DH;

    // Q tile 128x64: thread loads 32 bf16 (4 x uint4)
    {
        int r = tid >> 1, c0 = (tid & 1) * 32;
        const uint4* s = (const uint4*)(Qb + (size_t)(qbase + r)*DH + c0);
        uint4* d = (uint4*)&Qs[r*72 + c0];
        d[0] = s[0]; d[1] = s[1]; d[2] = s[2]; d[3] = s[3];
    }

    wmma::fragment<wmma::accumulator, 16, 16, 16, float> oacc[4];
    #pragma unroll
    for (int j = 0; j < 4; j++) wmma::fill_fragment(oacc[j], 0.0f);

    float lrow = 0.0f;
    int prow = tid >> 1, pcb = (tid & 1) * 32;   // exp-phase ownership

    // K/V prefetch: 64x64, thread owns 16 elems (2 x uint4 each)
    int kr = tid >> 2, kc = (tid & 3) * 16;
    int ktmax = 2*qt + 1;
    uint4 kreg0 = *(const uint4*)(Kb + (size_t)kr*DH + kc);
    uint4 kreg1 = *(const uint4*)(Kb + (size_t)kr*DH + kc + 8);
    uint4 vreg0 = *(const uint4*)(Vb + (size_t)kr*DH + kc);
    uint4 vreg1 = *(const uint4*)(Vb + (size_t)kr*DH + kc + 8);

    for (int kt = 0; kt <= ktmax; kt++) {
        int kbase = kt * BK;
        *(uint4*)&Ks[kr*72 + kc]     = kreg0;
        *(uint4*)&Ks[kr*72 + kc + 8] = kreg1;
        *(uint4*)&Vs[kr*72 + kc]     = vreg0;
        *(uint4*)&Vs[kr*72 + kc + 8] = vreg1;
        __syncthreads();
        if (kt < ktmax) {
            const __nv_bfloat16* kp = Kb + (size_t)(kbase + BK + kr)*DH + kc;
            const __half*        vp = Vb + (size_t)(kbase + BK + kr)*DH + kc;
            kreg0 = *(const uint4*)kp;  kreg1 = *(const uint4*)(kp + 8);
            vreg0 = *(const uint4*)vp;  vreg1 = *(const uint4*)(vp + 8);
        }

        // --- S = Q K^T : warp rows w*16, all 64 cols ---
        {
            wmma::fragment<wmma::accumulator, 16, 16, 16, float> sacc[4];
            #pragma unroll
            for (int j = 0; j < 4; j++) wmma::fill_fragment(sacc[j], 0.0f);
            #pragma unroll
            for (int kk = 0; kk < 64; kk += 16) {
                wmma::fragment<wmma::matrix_a, 16, 16, 16, __nv_bfloat16, wmma::row_major> a;
                wmma::load_matrix_sync(a, &Qs[w*16*72 + kk], 72);
                #pragma unroll
                for (int j = 0; j < 4; j++) {
                    wmma::fragment<wmma::matrix_b, 16, 16, 16, __nv_bfloat16, wmma::col_major> b;
                    wmma::load_matrix_sync(b, &Ks[j*16*72 + kk], 72);
                    wmma::mma_sync(sacc[j], a, b, sacc[j]);
                }
            }
            #pragma unroll
            for (int j = 0; j < 4; j++)
                wmma::store_matrix_sync(&Ps[w*16*68 + j*16], sacc[j], 68, wmma::mem_row_major);
        }
        __syncthreads();

        // --- P = exp(mask(S/8)) -> fp16 (vectorized), accumulate row sums ---
        {
            bool diag = (kt >= 2*qt);
            float psum = 0.0f;
            #pragma unroll
            for (int v4 = 0; v4 < 8; v4++) {
                int col = pcb + v4*4;
                float4 sv = *(const float4*)&Ps[prow*68 + col];
                float p0 = __expf(sv.x * 0.125f);
                float p1 = __expf(sv.y * 0.125f);
                float p2 = __expf(sv.z * 0.125f);
                float p3 = __expf(sv.w * 0.125f);
                if (diag) {
                    int lim = qbase + prow - kbase;   // keep col <= lim
                    if (col + 0 > lim) p0 = 0.0f;
                    if (col + 1 > lim) p1 = 0.0f;
                    if (col + 2 > lim) p2 = 0.0f;
                    if (col + 3 > lim) p3 = 0.0f;
                }
                __half2 h01 = __floats2half2_rn(p0, p1);
                __half2 h23 = __floats2half2_rn(p2, p3);
                *(__half2*)&Pf[prow*72 + col]     = h01;
                *(__half2*)&Pf[prow*72 + col + 2] = h23;
                psum += p0 + p1 + p2 + p3;
            }
            lrow += psum;
        }
        __syncthreads();

        // --- O += P V : warp rows w*16, 64 cols ---
        #pragma unroll
        for (int kk = 0; kk < 64; kk += 16) {
            wmma::fragment<wmma::matrix_a, 16, 16, 16, __half, wmma::row_major> a;
            wmma::load_matrix_sync(a, &Pf[w*16*72 + kk], 72);
            #pragma unroll
            for (int j = 0; j < 4; j++) {
                wmma::fragment<wmma::matrix_b, 16, 16, 16, __half, wmma::row_major> b;
                wmma::load_matrix_sync(b, &Vs[kk*72 + j*16], 72);
                wmma::mma_sync(oacc[j], a, b, oacc[j]);
            }
        }
        __syncthreads();
    }

    // --- epilogue: unnormalized O to gmem; 1/l to g_L ---
    int b_ = bh / HH, h = bh % HH;
    float* obase = g_Vh + ((size_t)(b_*NN + qbase + w*16))*DM + h*DH;
    #pragma unroll
    for (int j = 0; j < 4; j++)
        wmma::store_matrix_sync(obase + j*16, oacc[j], DM, wmma::mem_row_major);

    float l = lrow + __shfl_xor_sync(0xffffffffu, lrow, 1);
    if ((tid & 1) == 0)
        g_L[bh*NN + qbase + prow] = 1.0f / l;
}

// ---------------------------------------------------------------------------
extern "C" void kernel_launch(void* const* d_in, const int* in_sizes, int n_in,
                              void* d_out, int out_size) {
    const float* X  = (const float*)d_in[0];
    const float* Wq = (const float*)d_in[1];
    const float* Wk = (const float*)d_in[2];
    const float* Wv = (const float*)d_in[3];
    const float* Wo = (const float*)d_in[4];
    const float* bo = (const float*)d_in[5];
    float* out = (float*)d_out;

    cudaFuncSetAttribute(gemm_h<0>, cudaFuncAttributeMaxDynamicSharedMemorySize, SM_BYTES);
    cudaFuncSetAttribute(gemm_h<1>, cudaFuncAttributeMaxDynamicSharedMemorySize, SM_BYTES);
    cudaFuncSetAttribute(flash, cudaFuncAttributeMaxDynamicSharedMemorySize, FL_BYTES);

    // prepass: X and all weights -> fp16
    cvt_x<<<MROWS*DM/8/256, 256>>>(X);
    cvt_w<<<4*DM*DM/8/256, 256>>>(Wq, Wk, Wv, Wo);

    // fused QKV projection
    dim3 ggrid3(DM/TN, MROWS/TM, 3);
    gemm_h<1><<<ggrid3, 256, SM_BYTES>>>(nullptr, nullptr);

    int rows = BB*HH*NN;
    l2norm_cvt<<<rows*2*32/256, 256>>>(rows);
    vcvt<<<(MROWS*DM/4 + 255)/256, 256>>>();

    flash<<<dim3(NN/BQ, BB*HH), 256, FL_BYTES>>>();

    vh_norm<<<(MROWS*DM/8 + 255)/256, 256>>>();

    dim3 ggrid(DM/TN, MROWS/TM);
    gemm_h<0><<<ggrid, 256, SM_BYTES>>>(bo, out);
}